// round 1
// baseline (speedup 1.0000x reference)
#include <cuda_runtime.h>
#include <math.h>

#define M_TOTAL 32768
#define SEQ     8192
#define H       1024
#define NB      4

// Scratch (allocation-free rule: __device__ globals)
__device__ float g_Qf[(size_t)M_TOTAL * H];   // elu(Q)+1, fp32
__device__ float g_KV[NB * H];
__device__ float g_Ksum[NB * H];

__global__ void zero_kernel() {
    int i = blockIdx.x * blockDim.x + threadIdx.x;
    if (i < NB * H) { g_KV[i] = 0.f; g_Ksum[i] = 0.f; }
}

// ---------------------------------------------------------------------------
// Kernel 1: fused QKV GEMM + bias + elu+1 + per-channel sequence reduction.
// Block tile 128(M) x 64(N), K-step 16. 256 threads; each thread: 8x4 per
// matrix (3 matrices -> 96 accumulators).
// ---------------------------------------------------------------------------
__global__ __launch_bounds__(256) void qkv_kernel(
    const float* __restrict__ x,
    const float* __restrict__ wq, const float* __restrict__ bq,
    const float* __restrict__ wk, const float* __restrict__ bk,
    const float* __restrict__ wv, const float* __restrict__ bv)
{
    __shared__ float As[16][128];
    __shared__ float Bqs[16][64];
    __shared__ float Bks[16][64];
    __shared__ float Bvs[16][64];
    __shared__ float2 red[16][64];

    const int tid = threadIdx.x;
    const int m0 = blockIdx.y * 128;
    const int n0 = blockIdx.x * 64;
    const int tr = tid >> 4;   // 0..15 row group
    const int tc = tid & 15;   // 0..15 col group

    float accq[8][4] = {}, acck[8][4] = {}, accv[8][4] = {};

    for (int k0 = 0; k0 < H; k0 += 16) {
        // A tile: 128 x 16, 512 float4, 2 per thread, store transposed As[k][m]
        #pragma unroll
        for (int l = 0; l < 2; l++) {
            int idx = tid + l * 256;            // 0..511
            int row = idx >> 2;
            int kq  = (idx & 3) << 2;
            float4 v = *(const float4*)&x[(size_t)(m0 + row) * H + k0 + kq];
            As[kq + 0][row] = v.x; As[kq + 1][row] = v.y;
            As[kq + 2][row] = v.z; As[kq + 3][row] = v.w;
        }
        // B tiles: 16 x 64 each, 256 float4 each, 1 per thread per matrix
        {
            int row = tid >> 4;
            int col = (tid & 15) << 2;
            size_t g = (size_t)(k0 + row) * H + n0 + col;
            *(float4*)&Bqs[row][col] = *(const float4*)&wq[g];
            *(float4*)&Bks[row][col] = *(const float4*)&wk[g];
            *(float4*)&Bvs[row][col] = *(const float4*)&wv[g];
        }
        __syncthreads();

        #pragma unroll
        for (int k = 0; k < 16; k++) {
            float a[8];
            #pragma unroll
            for (int i = 0; i < 8; i++) a[i] = As[k][tr * 8 + i];
            float bq4[4], bk4[4], bv4[4];
            #pragma unroll
            for (int j = 0; j < 4; j++) {
                bq4[j] = Bqs[k][tc * 4 + j];
                bk4[j] = Bks[k][tc * 4 + j];
                bv4[j] = Bvs[k][tc * 4 + j];
            }
            #pragma unroll
            for (int i = 0; i < 8; i++)
                #pragma unroll
                for (int j = 0; j < 4; j++) {
                    accq[i][j] += a[i] * bq4[j];
                    acck[i][j] += a[i] * bk4[j];
                    accv[i][j] += a[i] * bv4[j];
                }
        }
        __syncthreads();
    }

    // Epilogue: bias, elu+1, write Qf, accumulate per-channel KV / Ksum
    const int batch = m0 / SEQ;   // 128-row tile never crosses a batch (8192 % 128 == 0)
    float pkv[4] = {}, pks[4] = {};
    #pragma unroll
    for (int j = 0; j < 4; j++) {
        int col = n0 + tc * 4 + j;
        float bqj = bq[col], bkj = bk[col], bvj = bv[col];
        #pragma unroll
        for (int i = 0; i < 8; i++) {
            float q  = accq[i][j] + bqj;
            float kk = acck[i][j] + bkj;
            float vv = accv[i][j] + bvj;
            float qf = (q  > 0.f) ? q  + 1.f : expf(q);    // elu(x)+1
            float kf = (kk > 0.f) ? kk + 1.f : expf(kk);
            g_Qf[(size_t)(m0 + tr * 8 + i) * H + col] = qf;
            pkv[j] += kf * vv;
            pks[j] += kf;
        }
    }
    #pragma unroll
    for (int j = 0; j < 4; j++)
        red[tr][tc * 4 + j] = make_float2(pkv[j], pks[j]);
    __syncthreads();
    if (tid < 64) {
        float skv = 0.f, sks = 0.f;
        #pragma unroll
        for (int r = 0; r < 16; r++) { skv += red[r][tid].x; sks += red[r][tid].y; }
        atomicAdd(&g_KV[batch * H + n0 + tid], skv);
        atomicAdd(&g_Ksum[batch * H + n0 + tid], sks);
    }
}

// ---------------------------------------------------------------------------
// Kernel 2: V' = Qf*KV / (Qf*Ksum + 1e-6)  (applied while staging A tile),
// then out = gelu_tanh(V' @ wo + bo).
// Block tile 128 x 128, K-step 16, 256 threads, 8x8 per thread.
// ---------------------------------------------------------------------------
__global__ __launch_bounds__(256) void out_kernel(
    const float* __restrict__ wo, const float* __restrict__ bo,
    float* __restrict__ out)
{
    __shared__ float As[16][128];
    __shared__ float Bs[16][128];
    __shared__ float kvs[H];
    __shared__ float kss[H];

    const int tid = threadIdx.x;
    const int m0 = blockIdx.y * 128;
    const int n0 = blockIdx.x * 128;
    const int batch = m0 / SEQ;
    const int tr = tid >> 4, tc = tid & 15;

    for (int i = tid; i < H; i += 256) {
        kvs[i] = g_KV[batch * H + i];
        kss[i] = g_Ksum[batch * H + i];
    }
    __syncthreads();

    float acc[8][8] = {};

    for (int k0 = 0; k0 < H; k0 += 16) {
        // A tile with normalization transform, stored transposed
        #pragma unroll
        for (int l = 0; l < 2; l++) {
            int idx = tid + l * 256;
            int row = idx >> 2;
            int kq  = (idx & 3) << 2;
            float4 v = *(const float4*)&g_Qf[(size_t)(m0 + row) * H + k0 + kq];
            float vv[4] = {v.x, v.y, v.z, v.w};
            #pragma unroll
            for (int j = 0; j < 4; j++) {
                int h = k0 + kq + j;
                float q = vv[j];
                float z = 1.0f / (q * kss[h] + 1e-6f);
                As[kq + j][row] = q * kvs[h] * z;
            }
        }
        // B tile: 16 x 128 = 512 float4, 2 per thread
        #pragma unroll
        for (int l = 0; l < 2; l++) {
            int idx = tid + l * 256;
            int row = idx >> 5;
            int col = (idx & 31) << 2;
            *(float4*)&Bs[row][col] = *(const float4*)&wo[(size_t)(k0 + row) * H + n0 + col];
        }
        __syncthreads();

        #pragma unroll
        for (int k = 0; k < 16; k++) {
            float a[8], b[8];
            #pragma unroll
            for (int i = 0; i < 8; i++) a[i] = As[k][tr * 8 + i];
            #pragma unroll
            for (int j = 0; j < 8; j++) b[j] = Bs[k][tc * 8 + j];
            #pragma unroll
            for (int i = 0; i < 8; i++)
                #pragma unroll
                for (int j = 0; j < 8; j++)
                    acc[i][j] += a[i] * b[j];
        }
        __syncthreads();
    }

    // gelu (tanh approximation) epilogue
    #pragma unroll
    for (int i = 0; i < 8; i++) {
        int m = m0 + tr * 8 + i;
        #pragma unroll
        for (int j = 0; j < 8; j++) {
            int c = n0 + tc * 8 + j;
            float v = acc[i][j] + bo[c];
            float t = 0.7978845608028654f * (v + 0.044715f * v * v * v);
            out[(size_t)m * H + c] = 0.5f * v * (1.0f + tanhf(t));
        }
    }
}

extern "C" void kernel_launch(void* const* d_in, const int* in_sizes, int n_in,
                              void* d_out, int out_size) {
    const float* x  = (const float*)d_in[0];
    const float* wq = (const float*)d_in[1];
    const float* bq = (const float*)d_in[2];
    const float* wk = (const float*)d_in[3];
    const float* bk = (const float*)d_in[4];
    const float* wv = (const float*)d_in[5];
    const float* bv = (const float*)d_in[6];
    const float* wo = (const float*)d_in[7];
    const float* bo = (const float*)d_in[8];
    float* out = (float*)d_out;

    zero_kernel<<<(NB * H + 255) / 256, 256>>>();

    dim3 g1(H / 64, M_TOTAL / 128);
    qkv_kernel<<<g1, 256>>>(x, wq, bq, wk, bk, wv, bv);

    dim3 g2(H / 128, M_TOTAL / 128);
    out_kernel<<<g2, 256>>>(wo, bo, out);
}

// round 3
// speedup vs baseline: 2.8930x; 2.8930x over previous
#include <cuda_runtime.h>
#include <cuda_bf16.h>
#include <cstdint>
#include <math.h>

#define M_TOTAL 32768
#define SEQ     8192
#define H       1024
#define NB      4
#define KP      3072                 // split-K: [hi | lo | hi]
#define KB      (KP*2)               // bytes per row of A'/B'
#define NCH     48                   // K chunks of 64 bf16 (128B)
#define STAGE_BYTES 32768            // 16KB A + 16KB B
#define SMEM_TOTAL (3*STAGE_BYTES)   // 96KB

// ---------------- scratch -----------------------------------------------
__device__ __nv_bfloat16 g_Ax[(size_t)M_TOTAL * KP];
__device__ __nv_bfloat16 g_Vp[(size_t)M_TOTAL * KP];
__device__ float         g_Qf[(size_t)M_TOTAL * H];
__device__ __nv_bfloat16 g_Bqkv[(size_t)3072 * KP];
__device__ __nv_bfloat16 g_Bo[(size_t)1024 * KP];
__device__ float         g_KV[NB * H];
__device__ float         g_Ksum[NB * H];

// ---------------- helpers ------------------------------------------------
__device__ __forceinline__ uint32_t smem_u32(const void* p) {
    uint32_t a;
    asm("{ .reg .u64 t; cvta.to.shared.u64 t, %1; cvt.u32.u64 %0, t; }" : "=r"(a) : "l"(p));
    return a;
}
__device__ __forceinline__ void cp16(uint32_t dst, const void* src) {
    asm volatile("cp.async.cg.shared.global [%0], [%1], 16;" :: "r"(dst), "l"(src));
}
__device__ __forceinline__ void cpcommit() {
    asm volatile("cp.async.commit_group;" ::: "memory");
}
template <int N> __device__ __forceinline__ void cpwait() {
    asm volatile("cp.async.wait_group %0;" :: "n"(N) : "memory");
}
__device__ __forceinline__ void ldmx4(uint32_t* r, uint32_t addr) {
    asm volatile("ldmatrix.sync.aligned.m8n8.x4.shared.b16 {%0,%1,%2,%3}, [%4];"
                 : "=r"(r[0]), "=r"(r[1]), "=r"(r[2]), "=r"(r[3]) : "r"(addr));
}
__device__ __forceinline__ void mma16816(float* d, const uint32_t* a, uint32_t b0, uint32_t b1) {
    asm volatile(
        "mma.sync.aligned.m16n8k16.row.col.f32.bf16.bf16.f32 "
        "{%0,%1,%2,%3}, {%4,%5,%6,%7}, {%8,%9}, {%0,%1,%2,%3};"
        : "+f"(d[0]), "+f"(d[1]), "+f"(d[2]), "+f"(d[3])
        : "r"(a[0]), "r"(a[1]), "r"(a[2]), "r"(a[3]), "r"(b0), "r"(b1));
}
__device__ __forceinline__ float elu1(float x) { return x > 0.f ? x + 1.f : __expf(x); }
__device__ __forceinline__ float gelu(float v) {
    float t = 0.7978845608028654f * (v + 0.044715f * v * v * v);
    return 0.5f * v * (1.0f + tanhf(t));
}

// ---------------- small kernels ------------------------------------------
__global__ void zero_kernel() {
    int i = blockIdx.x * blockDim.x + threadIdx.x;
    if (i < NB * H) { g_KV[i] = 0.f; g_Ksum[i] = 0.f; }
}

__global__ __launch_bounds__(256) void conv_x_kernel(const float* __restrict__ x) {
    int idx = blockIdx.x * 256 + threadIdx.x;
    int m = idx >> 8;
    int k = (idx & 255) << 2;
    float4 v = *(const float4*)&x[(size_t)m * H + k];
    __nv_bfloat16 h0 = __float2bfloat16(v.x), h1 = __float2bfloat16(v.y);
    __nv_bfloat16 h2 = __float2bfloat16(v.z), h3 = __float2bfloat16(v.w);
    __nv_bfloat16 l0 = __float2bfloat16(v.x - __bfloat162float(h0));
    __nv_bfloat16 l1 = __float2bfloat16(v.y - __bfloat162float(h1));
    __nv_bfloat16 l2 = __float2bfloat16(v.z - __bfloat162float(h2));
    __nv_bfloat16 l3 = __float2bfloat16(v.w - __bfloat162float(h3));
    __nv_bfloat16* row = &g_Ax[(size_t)m * KP];
    __nv_bfloat162* p;
    p = (__nv_bfloat162*)&row[k];        p[0] = {h0, h1}; p[1] = {h2, h3};
    p = (__nv_bfloat162*)&row[1024 + k]; p[0] = {l0, l1}; p[1] = {l2, l3};
    p = (__nv_bfloat162*)&row[2048 + k]; p[0] = {h0, h1}; p[1] = {h2, h3};
}

__global__ __launch_bounds__(256) void conv_w_kernel(
    const float* __restrict__ wq, const float* __restrict__ wk,
    const float* __restrict__ wv, const float* __restrict__ wo) {
    int h = blockIdx.x;
    int which = blockIdx.y;
    const float* w;
    __nv_bfloat16* row;
    if (which == 0)      { w = wq; row = &g_Bqkv[(size_t)h * KP]; }
    else if (which == 1) { w = wk; row = &g_Bqkv[(size_t)(1024 + (h >> 6) * 128 + (h & 63)) * KP]; }
    else if (which == 2) { w = wv; row = &g_Bqkv[(size_t)(1024 + (h >> 6) * 128 + 64 + (h & 63)) * KP]; }
    else                 { w = wo; row = &g_Bo[(size_t)h * KP]; }
    int k = threadIdx.x * 4;
    __nv_bfloat16 hi[4], lo[4];
    #pragma unroll
    for (int i = 0; i < 4; i++) {
        float v = __ldg(&w[(size_t)(k + i) * H + h]);
        hi[i] = __float2bfloat16(v);
        lo[i] = __float2bfloat16(v - __bfloat162float(hi[i]));
    }
    __nv_bfloat162* p;
    p = (__nv_bfloat162*)&row[k];        p[0] = {hi[0], hi[1]}; p[1] = {hi[2], hi[3]};
    p = (__nv_bfloat162*)&row[1024 + k]; p[0] = {hi[0], hi[1]}; p[1] = {hi[2], hi[3]};
    p = (__nv_bfloat162*)&row[2048 + k]; p[0] = {lo[0], lo[1]}; p[1] = {lo[2], lo[3]};
}

__global__ __launch_bounds__(256) void vprime_kernel() {
    int m = blockIdx.x;
    int bn = m / SEQ;
    int hh = threadIdx.x * 4;
    float4 q4 = *(const float4*)&g_Qf[(size_t)m * H + hh];
    float4 kv = *(const float4*)&g_KV[bn * H + hh];
    float4 ks = *(const float4*)&g_Ksum[bn * H + hh];
    float q[4] = {q4.x, q4.y, q4.z, q4.w};
    float a[4] = {kv.x, kv.y, kv.z, kv.w};
    float b[4] = {ks.x, ks.y, ks.z, ks.w};
    __nv_bfloat16 hi[4], lo[4];
    #pragma unroll
    for (int i = 0; i < 4; i++) {
        float vp = q[i] * a[i] * (1.0f / (q[i] * b[i] + 1e-6f));
        hi[i] = __float2bfloat16(vp);
        lo[i] = __float2bfloat16(vp - __bfloat162float(hi[i]));
    }
    __nv_bfloat16* row = &g_Vp[(size_t)m * KP];
    __nv_bfloat162* p;
    p = (__nv_bfloat162*)&row[hh];        p[0] = {hi[0], hi[1]}; p[1] = {hi[2], hi[3]};
    p = (__nv_bfloat162*)&row[1024 + hh]; p[0] = {lo[0], lo[1]}; p[1] = {lo[2], lo[3]};
    p = (__nv_bfloat162*)&row[2048 + hh]; p[0] = {hi[0], hi[1]}; p[1] = {hi[2], hi[3]};
}

// ---------------- HMMA GEMM ----------------------------------------------
// mode 0: [Q|K|V] = A'x . Bqkv^T ; Q tiles -> elu1 -> g_Qf ; K/V tiles -> reduction
// mode 1: out = Vp . Bo^T ; bias+gelu
__global__ __launch_bounds__(256, 2) void gemm_kernel(
    int mode,
    const float* __restrict__ b0p,
    const float* __restrict__ b1p,
    const float* __restrict__ b2p,
    float* __restrict__ outp)
{
    extern __shared__ __align__(1024) char smv[];
    const uint32_t sb = smem_u32(smv);
    const int tid = threadIdx.x;
    const int w = tid >> 5, l = tid & 31;

    const size_t m0 = (size_t)blockIdx.y * 128;
    const int n0 = blockIdx.x * 128;
    const __nv_bfloat16* A = mode ? g_Vp : g_Ax;
    const __nv_bfloat16* B = mode ? g_Bo : g_Bqkv;

    // cp.async source/dest (per thread: 4 A rows + 4 B rows, one 16B each)
    const char* Asrc = (const char*)A + (m0 + (tid >> 3)) * (size_t)KB + ((tid & 7) << 4);
    const char* Bsrc = (const char*)B + ((size_t)(n0 + (tid >> 3))) * KB + ((tid & 7) << 4);
    const uint32_t dst0 = ((tid >> 3) << 7) + ((((tid & 7) << 4)) ^ ((((tid >> 3) & 7)) << 4));

    auto load_chunk = [&](int ch, int s) {
        uint32_t sa = sb + s * STAGE_BYTES + dst0;
        uint32_t sbm = sa + 16384;
        const char* as = Asrc + (size_t)ch * 128;
        const char* bs = Bsrc + (size_t)ch * 128;
        #pragma unroll
        for (int j = 0; j < 4; j++) cp16(sa + (j << 12), as + j * (size_t)(32 * KB));
        #pragma unroll
        for (int j = 0; j < 4; j++) cp16(sbm + (j << 12), bs + j * (size_t)(32 * KB));
        cpcommit();
    };

    // ldmatrix lane geometry
    const int mw0 = w << 4;
    const uint32_t lx = (l & 7) << 4;
    const int arow = ((l >> 3) & 1) * 8 + (l & 7);
    const uint32_t ahb = (l >> 4) & 1;
    const int brow = ((l >> 4) & 1) * 8 + (l & 7);
    const uint32_t bhb = (l >> 3) & 1;
    const uint32_t arow128 = (uint32_t)(mw0 + arow) << 7;
    const uint32_t brow128 = (uint32_t)brow << 7;

    float acc[64];
    #pragma unroll
    for (int i = 0; i < 64; i++) acc[i] = 0.f;

    load_chunk(0, 0);
    load_chunk(1, 1);

    #pragma unroll 1
    for (int c = 0; c < NCH; c++) {
        if (c < NCH - 2) cpwait<1>(); else cpwait<0>();
        __syncthreads();
        if (c + 2 < NCH) load_chunk(c + 2, (c + 2) % 3);

        const uint32_t stA = sb + (c % 3) * STAGE_BYTES;
        const uint32_t stB = stA + 16384;
        #pragma unroll
        for (int ks = 0; ks < 4; ks++) {
            const uint32_t koffA = (((uint32_t)ks << 5) | (ahb << 4)) ^ lx;
            const uint32_t koffB = (((uint32_t)ks << 5) | (bhb << 4)) ^ lx;
            uint32_t af[4];
            ldmx4(af, stA + arow128 + koffA);
            uint32_t bf[32];
            #pragma unroll
            for (int j = 0; j < 8; j++)
                ldmx4(&bf[4 * j], stB + brow128 + ((uint32_t)j << 11) + koffB);
            #pragma unroll
            for (int t = 0; t < 16; t++)
                mma16816(&acc[4 * t], af, bf[2 * t], bf[2 * t + 1]);
        }
        __syncthreads();
    }

    // ------------- epilogue -------------
    const int r0 = mw0 + (l >> 2);      // warp rows r0, r0+8
    const int cl = (l & 3) << 1;

    if (mode == 0 && n0 >= 1024) {
        // K/V reduction tile: cols 0-63 = K channels, 64-127 = V (same h)
        const int pair64 = ((n0 - 1024) >> 7) << 6;
        const int bn = (int)(m0 / SEQ);
        float pkv[16], pks[16];
        #pragma unroll
        for (int i = 0; i < 16; i++) { pkv[i] = 0.f; pks[i] = 0.f; }
        #pragma unroll
        for (int t = 0; t < 8; t++) {
            #pragma unroll
            for (int i = 0; i < 4; i++) {
                int h = pair64 + 8 * t + cl + (i & 1);
                float kf = elu1(acc[4 * t + i] + __ldg(&b1p[h]));
                float vv = acc[4 * (t + 8) + i] + __ldg(&b2p[h]);
                int e = 2 * t + (i & 1);
                pkv[e] += kf * vv;
                pks[e] += kf;
            }
        }
        #pragma unroll
        for (int off = 16; off >= 4; off >>= 1)
            #pragma unroll
            for (int e = 0; e < 16; e++) {
                pkv[e] += __shfl_down_sync(0xffffffffu, pkv[e], off);
                pks[e] += __shfl_down_sync(0xffffffffu, pks[e], off);
            }
        float* redkv = (float*)smv;            // [8][64]
        float* redks = redkv + 8 * 64;
        if (l < 4) {
            #pragma unroll
            for (int t = 0; t < 8; t++)
                #pragma unroll
                for (int b = 0; b < 2; b++) {
                    int cc = 8 * t + 2 * l + b;
                    redkv[w * 64 + cc] = pkv[2 * t + b];
                    redks[w * 64 + cc] = pks[2 * t + b];
                }
        }
        __syncthreads();
        if (tid < 128) {
            int cc = tid & 63;
            float* src = (tid < 64) ? redkv : redks;
            float s = 0.f;
            #pragma unroll
            for (int ww = 0; ww < 8; ww++) s += src[ww * 64 + cc];
            float* dst = (tid < 64) ? &g_KV[bn * H + pair64 + cc] : &g_Ksum[bn * H + pair64 + cc];
            atomicAdd(dst, s);
        }
    } else {
        // Q tile (mode 0, elu1 -> g_Qf) or out tile (mode 1, gelu -> out)
        float* ep = (float*)smv;               // [128][132]
        #pragma unroll
        for (int t = 0; t < 16; t++) {
            int c0 = 8 * t + cl;
            float b0 = __ldg(&b0p[n0 + c0]);
            float b1 = __ldg(&b0p[n0 + c0 + 1]);
            float v0 = acc[4 * t + 0] + b0, v1 = acc[4 * t + 1] + b1;
            float v2 = acc[4 * t + 2] + b0, v3 = acc[4 * t + 3] + b1;
            if (mode == 0) { v0 = elu1(v0); v1 = elu1(v1); v2 = elu1(v2); v3 = elu1(v3); }
            else           { v0 = gelu(v0); v1 = gelu(v1); v2 = gelu(v2); v3 = gelu(v3); }
            ep[r0 * 132 + c0] = v0;       ep[r0 * 132 + c0 + 1] = v1;
            ep[(r0 + 8) * 132 + c0] = v2; ep[(r0 + 8) * 132 + c0 + 1] = v3;
        }
        __syncthreads();
        float* dst = (mode == 0) ? g_Qf : outp;
        #pragma unroll 8
        for (int i = 0; i < 64; i++) {
            int idx = i * 256 + tid;
            int rr = idx >> 7, cc = idx & 127;
            dst[(m0 + rr) * H + n0 + cc] = ep[rr * 132 + cc];
        }
    }
}

// ---------------- launch --------------------------------------------------
extern "C" void kernel_launch(void* const* d_in, const int* in_sizes, int n_in,
                              void* d_out, int out_size) {
    const float* x  = (const float*)d_in[0];
    const float* wq = (const float*)d_in[1];
    const float* bq = (const float*)d_in[2];
    const float* wk = (const float*)d_in[3];
    const float* bk = (const float*)d_in[4];
    const float* wv = (const float*)d_in[5];
    const float* bv = (const float*)d_in[6];
    const float* wo = (const float*)d_in[7];
    const float* bo = (const float*)d_in[8];
    float* out = (float*)d_out;

    cudaFuncSetAttribute(gemm_kernel, cudaFuncAttributeMaxDynamicSharedMemorySize, SMEM_TOTAL);

    zero_kernel<<<(NB * H + 255) / 256, 256>>>();
    conv_x_kernel<<<M_TOTAL, 256>>>(x);
    conv_w_kernel<<<dim3(1024, 4), 256>>>(wq, wk, wv, wo);

    gemm_kernel<<<dim3(24, M_TOTAL / 128), 256, SMEM_TOTAL>>>(0, bq, bk, bv, nullptr);
    vprime_kernel<<<M_TOTAL, 256>>>();
    gemm_kernel<<<dim3(8, M_TOTAL / 128), 256, SMEM_TOTAL>>>(1, bo, nullptr, nullptr, out);
}

// round 4
// speedup vs baseline: 3.3358x; 1.1530x over previous
#include <cuda_runtime.h>
#include <cuda_bf16.h>
#include <cstdint>
#include <math.h>

#define M_TOTAL 32768
#define SEQ     8192
#define H       1024
#define NB      4
#define KP      3072                 // split-K: [hi | lo | hi]
#define KB      (KP*2)               // bytes per row of A'/B'
#define NCH     48                   // K chunks of 64 bf16 (128B)
#define STAGE_BYTES 32768            // 16KB A + 16KB B
#define SMEM_TOTAL (3*STAGE_BYTES)   // 96KB

// ---------------- scratch -----------------------------------------------
__device__ __nv_bfloat16 g_Ax[(size_t)M_TOTAL * KP];
__device__ __nv_bfloat16 g_Vp[(size_t)M_TOTAL * KP];
__device__ float         g_Qf[(size_t)M_TOTAL * H];
__device__ __nv_bfloat16 g_Bqkv[(size_t)3072 * KP];
__device__ __nv_bfloat16 g_Bo[(size_t)1024 * KP];
__device__ float         g_KV[NB * H];
__device__ float         g_Ksum[NB * H];

// ---------------- helpers ------------------------------------------------
__device__ __forceinline__ uint32_t smem_u32(const void* p) {
    uint32_t a;
    asm("{ .reg .u64 t; cvta.to.shared.u64 t, %1; cvt.u32.u64 %0, t; }" : "=r"(a) : "l"(p));
    return a;
}
__device__ __forceinline__ void cp16(uint32_t dst, const void* src) {
    asm volatile("cp.async.cg.shared.global [%0], [%1], 16;" :: "r"(dst), "l"(src));
}
__device__ __forceinline__ void cpcommit() {
    asm volatile("cp.async.commit_group;" ::: "memory");
}
template <int N> __device__ __forceinline__ void cpwait() {
    asm volatile("cp.async.wait_group %0;" :: "n"(N) : "memory");
}
__device__ __forceinline__ void ldmx4(uint32_t* r, uint32_t addr) {
    asm volatile("ldmatrix.sync.aligned.m8n8.x4.shared.b16 {%0,%1,%2,%3}, [%4];"
                 : "=r"(r[0]), "=r"(r[1]), "=r"(r[2]), "=r"(r[3]) : "r"(addr));
}
__device__ __forceinline__ void mma16816(float* d, const uint32_t* a, uint32_t b0, uint32_t b1) {
    asm volatile(
        "mma.sync.aligned.m16n8k16.row.col.f32.bf16.bf16.f32 "
        "{%0,%1,%2,%3}, {%4,%5,%6,%7}, {%8,%9}, {%0,%1,%2,%3};"
        : "+f"(d[0]), "+f"(d[1]), "+f"(d[2]), "+f"(d[3])
        : "r"(a[0]), "r"(a[1]), "r"(a[2]), "r"(a[3]), "r"(b0), "r"(b1));
}
__device__ __forceinline__ float elu1(float x) { return x > 0.f ? x + 1.f : __expf(x); }
__device__ __forceinline__ float fast_tanh(float x) {
    float y;
    asm("tanh.approx.f32 %0, %1;" : "=f"(y) : "f"(x));
    return y;
}
__device__ __forceinline__ float gelu(float v) {
    float t = 0.7978845608028654f * (v + 0.044715f * v * v * v);
    return 0.5f * v * (1.0f + fast_tanh(t));
}

// ---------------- small kernels ------------------------------------------
__global__ void zero_kernel() {
    int i = blockIdx.x * blockDim.x + threadIdx.x;
    if (i < NB * H) { g_KV[i] = 0.f; g_Ksum[i] = 0.f; }
}

__global__ __launch_bounds__(256) void conv_x_kernel(const float* __restrict__ x) {
    int idx = blockIdx.x * 256 + threadIdx.x;
    int m = idx >> 8;
    int k = (idx & 255) << 2;
    float4 v = *(const float4*)&x[(size_t)m * H + k];
    __nv_bfloat16 h0 = __float2bfloat16(v.x), h1 = __float2bfloat16(v.y);
    __nv_bfloat16 h2 = __float2bfloat16(v.z), h3 = __float2bfloat16(v.w);
    __nv_bfloat16 l0 = __float2bfloat16(v.x - __bfloat162float(h0));
    __nv_bfloat16 l1 = __float2bfloat16(v.y - __bfloat162float(h1));
    __nv_bfloat16 l2 = __float2bfloat16(v.z - __bfloat162float(h2));
    __nv_bfloat16 l3 = __float2bfloat16(v.w - __bfloat162float(h3));
    __nv_bfloat16* row = &g_Ax[(size_t)m * KP];
    __nv_bfloat162* p;
    p = (__nv_bfloat162*)&row[k];        p[0] = {h0, h1}; p[1] = {h2, h3};
    p = (__nv_bfloat162*)&row[1024 + k]; p[0] = {l0, l1}; p[1] = {l2, l3};
    p = (__nv_bfloat162*)&row[2048 + k]; p[0] = {h0, h1}; p[1] = {h2, h3};
}

// weights -> B' rows, K-major, [hi | hi | lo]
// K/V interleave at 64-row blocks: [32 K-channels | 32 matching V-channels]
__global__ __launch_bounds__(256) void conv_w_kernel(
    const float* __restrict__ wq, const float* __restrict__ wk,
    const float* __restrict__ wv, const float* __restrict__ wo) {
    int h = blockIdx.x;
    int which = blockIdx.y;
    const float* w;
    __nv_bfloat16* row;
    if (which == 0)      { w = wq; row = &g_Bqkv[(size_t)h * KP]; }
    else if (which == 1) { w = wk; row = &g_Bqkv[(size_t)(1024 + (h >> 5) * 64 + (h & 31)) * KP]; }
    else if (which == 2) { w = wv; row = &g_Bqkv[(size_t)(1024 + (h >> 5) * 64 + 32 + (h & 31)) * KP]; }
    else                 { w = wo; row = &g_Bo[(size_t)h * KP]; }
    int k = threadIdx.x * 4;
    __nv_bfloat16 hi[4], lo[4];
    #pragma unroll
    for (int i = 0; i < 4; i++) {
        float v = __ldg(&w[(size_t)(k + i) * H + h]);
        hi[i] = __float2bfloat16(v);
        lo[i] = __float2bfloat16(v - __bfloat162float(hi[i]));
    }
    __nv_bfloat162* p;
    p = (__nv_bfloat162*)&row[k];        p[0] = {hi[0], hi[1]}; p[1] = {hi[2], hi[3]};
    p = (__nv_bfloat162*)&row[1024 + k]; p[0] = {hi[0], hi[1]}; p[1] = {hi[2], hi[3]};
    p = (__nv_bfloat162*)&row[2048 + k]; p[0] = {lo[0], lo[1]}; p[1] = {lo[2], lo[3]};
}

__global__ __launch_bounds__(256) void vprime_kernel() {
    int m = blockIdx.x;
    int bn = m / SEQ;
    int hh = threadIdx.x * 4;
    float4 q4 = *(const float4*)&g_Qf[(size_t)m * H + hh];
    float4 kv = *(const float4*)&g_KV[bn * H + hh];
    float4 ks = *(const float4*)&g_Ksum[bn * H + hh];
    float q[4] = {q4.x, q4.y, q4.z, q4.w};
    float a[4] = {kv.x, kv.y, kv.z, kv.w};
    float b[4] = {ks.x, ks.y, ks.z, ks.w};
    __nv_bfloat16 hi[4], lo[4];
    #pragma unroll
    for (int i = 0; i < 4; i++) {
        float vp = q[i] * a[i] * (1.0f / (q[i] * b[i] + 1e-6f));
        hi[i] = __float2bfloat16(vp);
        lo[i] = __float2bfloat16(vp - __bfloat162float(hi[i]));
    }
    __nv_bfloat16* row = &g_Vp[(size_t)m * KP];
    __nv_bfloat162* p;
    p = (__nv_bfloat162*)&row[hh];        p[0] = {hi[0], hi[1]}; p[1] = {hi[2], hi[3]};
    p = (__nv_bfloat162*)&row[1024 + hh]; p[0] = {lo[0], lo[1]}; p[1] = {lo[2], lo[3]};
    p = (__nv_bfloat162*)&row[2048 + hh]; p[0] = {hi[0], hi[1]}; p[1] = {hi[2], hi[3]};
}

// ---------------- HMMA GEMM ----------------------------------------------
// CTA tile 128x128, warp tile 32x64 (warp grid 4x2).
// mode 0: [Q|K|V] = A'x . Bqkv^T ; Q tiles -> elu1 -> g_Qf ; K/V tiles -> reduction
// mode 1: out = Vp . Bo^T ; bias+gelu
__global__ __launch_bounds__(256, 2) void gemm_kernel(
    int mode,
    const float* __restrict__ b0p,
    const float* __restrict__ b1p,
    const float* __restrict__ b2p,
    float* __restrict__ outp)
{
    extern __shared__ __align__(1024) char smv[];
    const uint32_t sb = smem_u32(smv);
    const int tid = threadIdx.x;
    const int w = tid >> 5, l = tid & 31;

    const size_t m0 = (size_t)blockIdx.y * 128;
    const int n0 = blockIdx.x * 128;
    const __nv_bfloat16* A = mode ? g_Vp : g_Ax;
    const __nv_bfloat16* B = mode ? g_Bo : g_Bqkv;

    // cp.async: per thread 4 A rows + 4 B rows, one 16B each
    const char* Asrc = (const char*)A + (m0 + (tid >> 3)) * (size_t)KB + ((tid & 7) << 4);
    const char* Bsrc = (const char*)B + ((size_t)(n0 + (tid >> 3))) * KB + ((tid & 7) << 4);
    const uint32_t dst0 = ((tid >> 3) << 7) + ((((tid & 7) << 4)) ^ ((((tid >> 3) & 7)) << 4));

    auto load_chunk = [&](int ch, int s) {
        uint32_t sa = sb + s * STAGE_BYTES + dst0;
        uint32_t sbm = sa + 16384;
        const char* as = Asrc + (size_t)ch * 128;
        const char* bs = Bsrc + (size_t)ch * 128;
        #pragma unroll
        for (int j = 0; j < 4; j++) cp16(sa + (j << 12), as + j * (size_t)(32 * KB));
        #pragma unroll
        for (int j = 0; j < 4; j++) cp16(sbm + (j << 12), bs + j * (size_t)(32 * KB));
        cpcommit();
    };

    // warp/lane geometry: warp tile 32(M) x 64(N)
    const int wm = (w & 3) << 5;          // 0,32,64,96
    const int wn = (w >> 2) << 6;         // 0,64
    const uint32_t lx = (l & 7) << 4;     // swizzle term (row&7 == l&7 for all frag loads)
    const int arow = ((l >> 3) & 1) * 8 + (l & 7);
    const uint32_t ahb = (l >> 4) & 1;
    const int brow = ((l >> 4) & 1) * 8 + (l & 7);
    const uint32_t bhb = (l >> 3) & 1;

    float acc[64];
    #pragma unroll
    for (int i = 0; i < 64; i++) acc[i] = 0.f;

    load_chunk(0, 0);
    load_chunk(1, 1);

    #pragma unroll 1
    for (int c = 0; c < NCH; c++) {
        if (c < NCH - 2) cpwait<1>(); else cpwait<0>();
        __syncthreads();
        if (c + 2 < NCH) load_chunk(c + 2, (c + 2) % 3);

        const uint32_t stA = sb + (c % 3) * STAGE_BYTES;
        const uint32_t stB = stA + 16384;
        #pragma unroll
        for (int ks = 0; ks < 4; ks++) {
            const uint32_t koffA = (((uint32_t)ks << 5) | (ahb << 4)) ^ lx;
            const uint32_t koffB = (((uint32_t)ks << 5) | (bhb << 4)) ^ lx;
            uint32_t af[2][4];
            #pragma unroll
            for (int mt = 0; mt < 2; mt++)
                ldmx4(af[mt], stA + ((uint32_t)(wm + mt * 16 + arow) << 7) + koffA);
            uint32_t bf[4][4];
            #pragma unroll
            for (int j = 0; j < 4; j++)
                ldmx4(bf[j], stB + ((uint32_t)(wn + j * 16 + brow) << 7) + koffB);
            #pragma unroll
            for (int mt = 0; mt < 2; mt++)
                #pragma unroll
                for (int nt = 0; nt < 8; nt++)
                    mma16816(&acc[(mt * 8 + nt) * 4], af[mt],
                             bf[nt >> 1][(nt & 1) * 2], bf[nt >> 1][(nt & 1) * 2 + 1]);
        }
        __syncthreads();
    }

    // ------------- epilogue -------------
    const int cl = (l & 3) << 1;

    if (mode == 0 && n0 >= 1024) {
        // KV tile: each warp's 64 cols = [32 K-ch | 32 matching V-ch]; pair nt <-> nt+4
        const int hbase = ((n0 - 1024) >> 6) * 32;     // CTA covers h hbase..hbase+63
        const int hw = hbase + (wn >> 1);              // this warp's 32-ch block
        const int bn = (int)(m0 / SEQ);
        float pkv[8], pks[8];
        #pragma unroll
        for (int i = 0; i < 8; i++) { pkv[i] = 0.f; pks[i] = 0.f; }
        #pragma unroll
        for (int mt = 0; mt < 2; mt++)
            #pragma unroll
            for (int nt = 0; nt < 4; nt++)
                #pragma unroll
                for (int i = 0; i < 4; i++) {
                    int hl = nt * 8 + cl + (i & 1);
                    float kf = elu1(acc[(mt * 8 + nt) * 4 + i] + __ldg(&b1p[hw + hl]));
                    float vv = acc[(mt * 8 + nt + 4) * 4 + i] + __ldg(&b2p[hw + hl]);
                    int e = nt * 2 + (i & 1);
                    pkv[e] += kf * vv;
                    pks[e] += kf;
                }
        #pragma unroll
        for (int off = 16; off >= 4; off >>= 1)
            #pragma unroll
            for (int e = 0; e < 8; e++) {
                pkv[e] += __shfl_down_sync(0xffffffffu, pkv[e], off);
                pks[e] += __shfl_down_sync(0xffffffffu, pks[e], off);
            }
        float* redkv = (float*)smv;          // [8 warps][32]
        float* redks = redkv + 8 * 32;
        if (l < 4) {
            #pragma unroll
            for (int e = 0; e < 8; e++) {
                int hl = (e >> 1) * 8 + l * 2 + (e & 1);
                redkv[w * 32 + hl] = pkv[e];
                redks[w * 32 + hl] = pks[e];
            }
        }
        __syncthreads();
        if (tid < 128) {
            int cc = tid & 63;
            int w0 = (cc >> 5) * 4;          // warps 0-3 (cols 0-63) or 4-7 (64-127)
            float* src = (tid < 64) ? redkv : redks;
            float s = 0.f;
            #pragma unroll
            for (int j = 0; j < 4; j++) s += src[(w0 + j) * 32 + (cc & 31)];
            float* dst = (tid < 64) ? &g_KV[bn * H + hbase + cc]
                                    : &g_Ksum[bn * H + hbase + cc];
            atomicAdd(dst, s);
        }
    } else {
        // Q tile (mode 0, elu1 -> g_Qf) or out tile (mode 1, gelu -> out)
        float* ep = (float*)smv;             // [128][132]
        #pragma unroll
        for (int mt = 0; mt < 2; mt++)
            #pragma unroll
            for (int nt = 0; nt < 8; nt++) {
                int c0 = wn + nt * 8 + cl;
                float bb0 = __ldg(&b0p[n0 + c0]);
                float bb1 = __ldg(&b0p[n0 + c0 + 1]);
                int r0 = wm + mt * 16 + (l >> 2);
                float v0 = acc[(mt * 8 + nt) * 4 + 0] + bb0;
                float v1 = acc[(mt * 8 + nt) * 4 + 1] + bb1;
                float v2 = acc[(mt * 8 + nt) * 4 + 2] + bb0;
                float v3 = acc[(mt * 8 + nt) * 4 + 3] + bb1;
                if (mode == 0) { v0 = elu1(v0); v1 = elu1(v1); v2 = elu1(v2); v3 = elu1(v3); }
                else           { v0 = gelu(v0); v1 = gelu(v1); v2 = gelu(v2); v3 = gelu(v3); }
                ep[r0 * 132 + c0] = v0;        ep[r0 * 132 + c0 + 1] = v1;
                ep[(r0 + 8) * 132 + c0] = v2;  ep[(r0 + 8) * 132 + c0 + 1] = v3;
            }
        __syncthreads();
        float* dst = (mode == 0) ? g_Qf : outp;
        #pragma unroll 8
        for (int i = 0; i < 64; i++) {
            int idx = i * 256 + tid;
            int rr = idx >> 7, cc = idx & 127;
            dst[(m0 + rr) * H + n0 + cc] = ep[rr * 132 + cc];
        }
    }
}

// ---------------- launch --------------------------------------------------
extern "C" void kernel_launch(void* const* d_in, const int* in_sizes, int n_in,
                              void* d_out, int out_size) {
    const float* x  = (const float*)d_in[0];
    const float* wq = (const float*)d_in[1];
    const float* bq = (const float*)d_in[2];
    const float* wk = (const float*)d_in[3];
    const float* bk = (const float*)d_in[4];
    const float* wv = (const float*)d_in[5];
    const float* bv = (const float*)d_in[6];
    const float* wo = (const float*)d_in[7];
    const float* bo = (const float*)d_in[8];
    float* out = (float*)d_out;

    cudaFuncSetAttribute(gemm_kernel, cudaFuncAttributeMaxDynamicSharedMemorySize, SMEM_TOTAL);

    zero_kernel<<<(NB * H + 255) / 256, 256>>>();
    conv_x_kernel<<<M_TOTAL, 256>>>(x);
    conv_w_kernel<<<dim3(1024, 4), 256>>>(wq, wk, wv, wo);

    gemm_kernel<<<dim3(24, M_TOTAL / 128), 256, SMEM_TOTAL>>>(0, bq, bk, bv, nullptr);
    vprime_kernel<<<M_TOTAL, 256>>>();
    gemm_kernel<<<dim3(8, M_TOTAL / 128), 256, SMEM_TOTAL>>>(1, bo, nullptr, nullptr, out);
}

// round 5
// speedup vs baseline: 3.9191x; 1.1749x over previous
#include <cuda_runtime.h>
#include <cuda_bf16.h>
#include <cstdint>
#include <math.h>

#define M_TOTAL 32768
#define SEQ     8192
#define H       1024
#define NB      4
#define KPA     2048                 // physical A cols: [hi | lo]
#define KBA     (KPA*2)              // 4096 B per A row
#define STAGE_BYTES 32768            // 16KB A + 16KB B
#define SMEM_TOTAL (3*STAGE_BYTES)   // 96KB

// ---------------- scratch -----------------------------------------------
__device__ __nv_bfloat16 g_Ax[(size_t)M_TOTAL * KPA];   // x: [hi|lo]
__device__ __nv_bfloat16 g_Vp[(size_t)M_TOTAL * KPA];   // V': [hi|lo]
__device__ __nv_bfloat16 g_Qf[(size_t)M_TOTAL * H];     // elu(q)+1, bf16
__device__ __nv_bfloat16 g_Bkv[(size_t)2048 * KPA];     // K/V interleaved rows, [hi|lo]
__device__ __nv_bfloat16 g_Bq [(size_t)1024 * 1024];    // Q weights, hi only
__device__ __nv_bfloat16 g_Bo [(size_t)1024 * KPA];     // out weights, [hi|lo]
__device__ float         g_KV[NB * H];
__device__ float         g_Ksum[NB * H];

// ---------------- helpers ------------------------------------------------
__device__ __forceinline__ uint32_t smem_u32(const void* p) {
    uint32_t a;
    asm("{ .reg .u64 t; cvta.to.shared.u64 t, %1; cvt.u32.u64 %0, t; }" : "=r"(a) : "l"(p));
    return a;
}
__device__ __forceinline__ void cp16(uint32_t dst, const void* src) {
    asm volatile("cp.async.cg.shared.global [%0], [%1], 16;" :: "r"(dst), "l"(src));
}
__device__ __forceinline__ void cpcommit() {
    asm volatile("cp.async.commit_group;" ::: "memory");
}
template <int N> __device__ __forceinline__ void cpwait() {
    asm volatile("cp.async.wait_group %0;" :: "n"(N) : "memory");
}
__device__ __forceinline__ void ldmx4(uint32_t* r, uint32_t addr) {
    asm volatile("ldmatrix.sync.aligned.m8n8.x4.shared.b16 {%0,%1,%2,%3}, [%4];"
                 : "=r"(r[0]), "=r"(r[1]), "=r"(r[2]), "=r"(r[3]) : "r"(addr));
}
__device__ __forceinline__ void mma16816(float* d, const uint32_t* a, uint32_t b0, uint32_t b1) {
    asm volatile(
        "mma.sync.aligned.m16n8k16.row.col.f32.bf16.bf16.f32 "
        "{%0,%1,%2,%3}, {%4,%5,%6,%7}, {%8,%9}, {%0,%1,%2,%3};"
        : "+f"(d[0]), "+f"(d[1]), "+f"(d[2]), "+f"(d[3])
        : "r"(a[0]), "r"(a[1]), "r"(a[2]), "r"(a[3]), "r"(b0), "r"(b1));
}
__device__ __forceinline__ float elu1(float x) { return x > 0.f ? x + 1.f : __expf(x); }
__device__ __forceinline__ float fast_tanh(float x) {
    float y;
    asm("tanh.approx.f32 %0, %1;" : "=f"(y) : "f"(x));
    return y;
}
__device__ __forceinline__ float gelu(float v) {
    float t = 0.7978845608028654f * (v + 0.044715f * v * v * v);
    return 0.5f * v * (1.0f + fast_tanh(t));
}

// ---------------- small kernels ------------------------------------------
__global__ void zero_kernel() {
    int i = blockIdx.x * blockDim.x + threadIdx.x;
    if (i < NB * H) { g_KV[i] = 0.f; g_Ksum[i] = 0.f; }
}

__global__ __launch_bounds__(256) void conv_x_kernel(const float* __restrict__ x) {
    int idx = blockIdx.x * 256 + threadIdx.x;
    int m = idx >> 8;
    int k = (idx & 255) << 2;
    float4 v = *(const float4*)&x[(size_t)m * H + k];
    __nv_bfloat16 h0 = __float2bfloat16(v.x), h1 = __float2bfloat16(v.y);
    __nv_bfloat16 h2 = __float2bfloat16(v.z), h3 = __float2bfloat16(v.w);
    __nv_bfloat16 l0 = __float2bfloat16(v.x - __bfloat162float(h0));
    __nv_bfloat16 l1 = __float2bfloat16(v.y - __bfloat162float(h1));
    __nv_bfloat16 l2 = __float2bfloat16(v.z - __bfloat162float(h2));
    __nv_bfloat16 l3 = __float2bfloat16(v.w - __bfloat162float(h3));
    __nv_bfloat16* row = &g_Ax[(size_t)m * KPA];
    __nv_bfloat162* p;
    p = (__nv_bfloat162*)&row[k];        p[0] = {h0, h1}; p[1] = {h2, h3};
    p = (__nv_bfloat162*)&row[1024 + k]; p[0] = {l0, l1}; p[1] = {l2, l3};
}

// weights -> B' rows, K-major. Q: hi only. K/V: interleaved 64-blocks
// [32 K-ch | 32 matching V-ch], [hi|lo]. O: [hi|lo].
__global__ __launch_bounds__(256) void conv_w_kernel(
    const float* __restrict__ wq, const float* __restrict__ wk,
    const float* __restrict__ wv, const float* __restrict__ wo) {
    int h = blockIdx.x;
    int which = blockIdx.y;
    const float* w;
    __nv_bfloat16* row;
    if (which == 0)      { w = wq; row = &g_Bq[(size_t)h * 1024]; }
    else if (which == 1) { w = wk; row = &g_Bkv[(size_t)((h >> 5) * 64 + (h & 31)) * KPA]; }
    else if (which == 2) { w = wv; row = &g_Bkv[(size_t)((h >> 5) * 64 + 32 + (h & 31)) * KPA]; }
    else                 { w = wo; row = &g_Bo[(size_t)h * KPA]; }
    int k = threadIdx.x * 4;
    __nv_bfloat16 hi[4], lo[4];
    #pragma unroll
    for (int i = 0; i < 4; i++) {
        float v = __ldg(&w[(size_t)(k + i) * H + h]);
        hi[i] = __float2bfloat16(v);
        lo[i] = __float2bfloat16(v - __bfloat162float(hi[i]));
    }
    __nv_bfloat162* p = (__nv_bfloat162*)&row[k];
    p[0] = {hi[0], hi[1]}; p[1] = {hi[2], hi[3]};
    if (which != 0) {
        p = (__nv_bfloat162*)&row[1024 + k];
        p[0] = {lo[0], lo[1]}; p[1] = {lo[2], lo[3]};
    }
}

// V' = Qf*KV / (Qf*Ksum + 1e-6) -> split bf16 [hi|lo]
__global__ __launch_bounds__(256) void vprime_kernel() {
    int m = blockIdx.x;
    int bn = m / SEQ;
    int hh = threadIdx.x * 4;
    const __nv_bfloat162* qp = (const __nv_bfloat162*)&g_Qf[(size_t)m * H + hh];
    __nv_bfloat162 q01 = qp[0], q23 = qp[1];
    float q[4] = {__bfloat162float(q01.x), __bfloat162float(q01.y),
                  __bfloat162float(q23.x), __bfloat162float(q23.y)};
    float4 kv = *(const float4*)&g_KV[bn * H + hh];
    float4 ks = *(const float4*)&g_Ksum[bn * H + hh];
    float a[4] = {kv.x, kv.y, kv.z, kv.w};
    float b[4] = {ks.x, ks.y, ks.z, ks.w};
    __nv_bfloat16 hi[4], lo[4];
    #pragma unroll
    for (int i = 0; i < 4; i++) {
        float vp = q[i] * a[i] * (1.0f / (q[i] * b[i] + 1e-6f));
        hi[i] = __float2bfloat16(vp);
        lo[i] = __float2bfloat16(vp - __bfloat162float(hi[i]));
    }
    __nv_bfloat16* row = &g_Vp[(size_t)m * KPA];
    __nv_bfloat162* p;
    p = (__nv_bfloat162*)&row[hh];        p[0] = {hi[0], hi[1]}; p[1] = {hi[2], hi[3]};
    p = (__nv_bfloat162*)&row[1024 + hh]; p[0] = {lo[0], lo[1]}; p[1] = {lo[2], lo[3]};
}

// ---------------- HMMA GEMM ----------------------------------------------
// CTA tile 128x128, warp tile 32x64 (warp grid 4x2), single-sync 3-stage pipe.
// MODE 0: KV-GEMM  A=g_Ax (K'=3072 logical) x g_Bkv -> per-channel reduction
// MODE 1: out-GEMM A=g_Vp x g_Bo -> bias+gelu -> out
// MODE 2: Q-GEMM   A=g_Ax(hi) x g_Bq (K=1024 plain) -> elu1 -> g_Qf (bf16)
template <int MODE, int NCHT>
__global__ __launch_bounds__(256, 2) void gemm_kernel(
    const float* __restrict__ b0p,
    const float* __restrict__ b1p,
    const float* __restrict__ b2p,
    float* __restrict__ outp)
{
    extern __shared__ __align__(1024) char smv[];
    const uint32_t sb = smem_u32(smv);
    const int tid = threadIdx.x;
    const int w = tid >> 5, l = tid & 31;

    const size_t m0 = (size_t)blockIdx.y * 128;
    const int n0 = blockIdx.x * 128;

    const __nv_bfloat16* A = (MODE == 1) ? g_Vp : g_Ax;
    const __nv_bfloat16* B = (MODE == 0) ? g_Bkv : ((MODE == 1) ? g_Bo : g_Bq);
    constexpr int KBB = (MODE == 2) ? 2048 : 4096;   // bytes per B row

    const char* Asrc = (const char*)A + (m0 + (tid >> 3)) * (size_t)KBA + ((tid & 7) << 4);
    const char* Bsrc = (const char*)B + ((size_t)(n0 + (tid >> 3))) * KBB + ((tid & 7) << 4);
    const uint32_t dst0 = ((tid >> 3) << 7) + ((((tid & 7) << 4)) ^ ((((tid >> 3) & 7)) << 4));

    auto load_chunk = [&](int ch, int s) {
        int chA = (ch < 32) ? ch : ch - 32;        // [hi|lo|hi] -> phys [hi|lo]
        int chB = (ch < 16) ? ch : ch - 16;        // [hi|hi|lo] -> phys [hi|lo]
        uint32_t sa = sb + s * STAGE_BYTES + dst0;
        uint32_t sbm = sa + 16384;
        const char* as = Asrc + (size_t)chA * 128;
        const char* bs = Bsrc + (size_t)chB * 128;
        #pragma unroll
        for (int j = 0; j < 4; j++) cp16(sa + (j << 12), as + j * (size_t)(32 * KBA));
        #pragma unroll
        for (int j = 0; j < 4; j++) cp16(sbm + (j << 12), bs + j * (size_t)(32 * KBB));
        cpcommit();
    };

    // warp/lane geometry: warp tile 32(M) x 64(N)
    const int wm = (w & 3) << 5;
    const int wn = (w >> 2) << 6;
    const uint32_t lx = (l & 7) << 4;
    const int arow = ((l >> 3) & 1) * 8 + (l & 7);
    const uint32_t ahb = (l >> 4) & 1;
    const int brow = ((l >> 4) & 1) * 8 + (l & 7);
    const uint32_t bhb = (l >> 3) & 1;

    float acc[64];
    #pragma unroll
    for (int i = 0; i < 64; i++) acc[i] = 0.f;

    load_chunk(0, 0);
    load_chunk(1, 1);

    #pragma unroll 1
    for (int c = 0; c < NCHT; c++) {
        if (c < NCHT - 2) cpwait<1>(); else cpwait<0>();
        __syncthreads();
        if (c + 2 < NCHT) load_chunk(c + 2, (c + 2) % 3);

        const uint32_t stA = sb + (c % 3) * STAGE_BYTES;
        const uint32_t stB = stA + 16384;
        #pragma unroll
        for (int ks = 0; ks < 4; ks++) {
            const uint32_t koffA = (((uint32_t)ks << 5) | (ahb << 4)) ^ lx;
            const uint32_t koffB = (((uint32_t)ks << 5) | (bhb << 4)) ^ lx;
            uint32_t af[2][4];
            #pragma unroll
            for (int mt = 0; mt < 2; mt++)
                ldmx4(af[mt], stA + ((uint32_t)(wm + mt * 16 + arow) << 7) + koffA);
            uint32_t bf[4][4];
            #pragma unroll
            for (int j = 0; j < 4; j++)
                ldmx4(bf[j], stB + ((uint32_t)(wn + j * 16 + brow) << 7) + koffB);
            #pragma unroll
            for (int mt = 0; mt < 2; mt++)
                #pragma unroll
                for (int nt = 0; nt < 8; nt++)
                    mma16816(&acc[(mt * 8 + nt) * 4], af[mt],
                             bf[nt >> 1][(nt & 1) * 2], bf[nt >> 1][(nt & 1) * 2 + 1]);
        }
    }
    __syncthreads();   // retire last-stage reads before smem reuse in epilogue

    // ------------- epilogue -------------
    const int cl = (l & 3) << 1;

    if (MODE == 0) {
        // KV tile: warp's 64 cols = [32 K-ch | 32 matching V-ch]; pair nt <-> nt+4
        const int hbase = (n0 >> 6) * 32;
        const int hw = hbase + (wn >> 1);
        const int bn = (int)(m0 / SEQ);
        float pkv[8], pks[8];
        #pragma unroll
        for (int i = 0; i < 8; i++) { pkv[i] = 0.f; pks[i] = 0.f; }
        #pragma unroll
        for (int mt = 0; mt < 2; mt++)
            #pragma unroll
            for (int nt = 0; nt < 4; nt++)
                #pragma unroll
                for (int i = 0; i < 4; i++) {
                    int hl = nt * 8 + cl + (i & 1);
                    float kf = elu1(acc[(mt * 8 + nt) * 4 + i] + __ldg(&b1p[hw + hl]));
                    float vv = acc[(mt * 8 + nt + 4) * 4 + i] + __ldg(&b2p[hw + hl]);
                    int e = nt * 2 + (i & 1);
                    pkv[e] += kf * vv;
                    pks[e] += kf;
                }
        #pragma unroll
        for (int off = 16; off >= 4; off >>= 1)
            #pragma unroll
            for (int e = 0; e < 8; e++) {
                pkv[e] += __shfl_down_sync(0xffffffffu, pkv[e], off);
                pks[e] += __shfl_down_sync(0xffffffffu, pks[e], off);
            }
        float* redkv = (float*)smv;          // [8 warps][32]
        float* redks = redkv + 8 * 32;
        if (l < 4) {
            #pragma unroll
            for (int e = 0; e < 8; e++) {
                int hl = (e >> 1) * 8 + l * 2 + (e & 1);
                redkv[w * 32 + hl] = pkv[e];
                redks[w * 32 + hl] = pks[e];
            }
        }
        __syncthreads();
        if (tid < 128) {
            int cc = tid & 63;
            int w0 = (cc >> 5) * 4;
            float* src = (tid < 64) ? redkv : redks;
            float s = 0.f;
            #pragma unroll
            for (int j = 0; j < 4; j++) s += src[(w0 + j) * 32 + (cc & 31)];
            float* dst = (tid < 64) ? &g_KV[bn * H + hbase + cc]
                                    : &g_Ksum[bn * H + hbase + cc];
            atomicAdd(dst, s);
        }
    } else {
        // MODE 2: elu1 -> g_Qf (bf16). MODE 1: gelu -> out (fp32).
        float* ep = (float*)smv;             // [128][132]
        #pragma unroll
        for (int mt = 0; mt < 2; mt++)
            #pragma unroll
            for (int nt = 0; nt < 8; nt++) {
                int c0 = wn + nt * 8 + cl;
                float bb0 = __ldg(&b0p[n0 + c0]);
                float bb1 = __ldg(&b0p[n0 + c0 + 1]);
                int r0 = wm + mt * 16 + (l >> 2);
                float v0 = acc[(mt * 8 + nt) * 4 + 0] + bb0;
                float v1 = acc[(mt * 8 + nt) * 4 + 1] + bb1;
                float v2 = acc[(mt * 8 + nt) * 4 + 2] + bb0;
                float v3 = acc[(mt * 8 + nt) * 4 + 3] + bb1;
                if (MODE == 2) { v0 = elu1(v0); v1 = elu1(v1); v2 = elu1(v2); v3 = elu1(v3); }
                else           { v0 = gelu(v0); v1 = gelu(v1); v2 = gelu(v2); v3 = gelu(v3); }
                ep[r0 * 132 + c0] = v0;        ep[r0 * 132 + c0 + 1] = v1;
                ep[(r0 + 8) * 132 + c0] = v2;  ep[(r0 + 8) * 132 + c0 + 1] = v3;
            }
        __syncthreads();
        if (MODE == 2) {
            #pragma unroll 8
            for (int i = 0; i < 64; i++) {
                int idx = i * 256 + tid;
                int rr = idx >> 7, cc = idx & 127;
                g_Qf[(m0 + rr) * H + n0 + cc] = __float2bfloat16(ep[rr * 132 + cc]);
            }
        } else {
            #pragma unroll 8
            for (int i = 0; i < 64; i++) {
                int idx = i * 256 + tid;
                int rr = idx >> 7, cc = idx & 127;
                outp[(m0 + rr) * H + n0 + cc] = ep[rr * 132 + cc];
            }
        }
    }
}

// ---------------- launch --------------------------------------------------
extern "C" void kernel_launch(void* const* d_in, const int* in_sizes, int n_in,
                              void* d_out, int out_size) {
    const float* x  = (const float*)d_in[0];
    const float* wq = (const float*)d_in[1];
    const float* bq = (const float*)d_in[2];
    const float* wk = (const float*)d_in[3];
    const float* bk = (const float*)d_in[4];
    const float* wv = (const float*)d_in[5];
    const float* bv = (const float*)d_in[6];
    const float* wo = (const float*)d_in[7];
    const float* bo = (const float*)d_in[8];
    float* out = (float*)d_out;

    cudaFuncSetAttribute(gemm_kernel<0, 48>, cudaFuncAttributeMaxDynamicSharedMemorySize, SMEM_TOTAL);
    cudaFuncSetAttribute(gemm_kernel<1, 48>, cudaFuncAttributeMaxDynamicSharedMemorySize, SMEM_TOTAL);
    cudaFuncSetAttribute(gemm_kernel<2, 16>, cudaFuncAttributeMaxDynamicSharedMemorySize, SMEM_TOTAL);

    zero_kernel<<<(NB * H + 255) / 256, 256>>>();
    conv_x_kernel<<<M_TOTAL, 256>>>(x);
    conv_w_kernel<<<dim3(1024, 4), 256>>>(wq, wk, wv, wo);

    gemm_kernel<2, 16><<<dim3(8,  M_TOTAL / 128), 256, SMEM_TOTAL>>>(bq, nullptr, nullptr, nullptr);
    gemm_kernel<0, 48><<<dim3(16, M_TOTAL / 128), 256, SMEM_TOTAL>>>(nullptr, bk, bv, nullptr);
    vprime_kernel<<<M_TOTAL, 256>>>();
    gemm_kernel<1, 48><<<dim3(8,  M_TOTAL / 128), 256, SMEM_TOTAL>>>(bo, nullptr, nullptr, out);
}

// round 6
// speedup vs baseline: 5.3949x; 1.3766x over previous
#include <cuda_runtime.h>
#include <cuda_fp16.h>
#include <cstdint>
#include <math.h>

#define M_TOTAL 32768
#define SEQ     8192
#define H       1024
#define NB      4
#define KPA     2048                 // physical A cols: [hi | lo] fp16
#define KBA     (KPA*2)              // 4096 B per A row
#define KBB     2048                 // B rows: 1024 fp16 cols (hi only)
#define STAGE_BYTES 32768            // 16KB A + 16KB B
#define SMEM_TOTAL (3*STAGE_BYTES)   // 96KB

// ---------------- scratch -----------------------------------------------
__device__ __half g_Ax[(size_t)M_TOTAL * KPA];   // x: [hi|lo] fp16
__device__ __half g_Vp[(size_t)M_TOTAL * KPA];   // V': [hi|lo] fp16
__device__ __half g_Qf[(size_t)M_TOTAL * H];     // elu(q)+1, fp16
__device__ __half g_Bkv[(size_t)2048 * 1024];    // K/V interleaved rows, hi
__device__ __half g_Bq [(size_t)1024 * 1024];    // Q weights, hi
__device__ __half g_Bo [(size_t)1024 * 1024];    // out weights, hi
__device__ float  g_KV[NB * H];
__device__ float  g_Ksum[NB * H];

// ---------------- helpers ------------------------------------------------
__device__ __forceinline__ uint32_t smem_u32(const void* p) {
    uint32_t a;
    asm("{ .reg .u64 t; cvta.to.shared.u64 t, %1; cvt.u32.u64 %0, t; }" : "=r"(a) : "l"(p));
    return a;
}
__device__ __forceinline__ void cp16(uint32_t dst, const void* src) {
    asm volatile("cp.async.cg.shared.global [%0], [%1], 16;" :: "r"(dst), "l"(src));
}
__device__ __forceinline__ void cpcommit() {
    asm volatile("cp.async.commit_group;" ::: "memory");
}
template <int N> __device__ __forceinline__ void cpwait() {
    asm volatile("cp.async.wait_group %0;" :: "n"(N) : "memory");
}
__device__ __forceinline__ void ldmx4(uint32_t* r, uint32_t addr) {
    asm volatile("ldmatrix.sync.aligned.m8n8.x4.shared.b16 {%0,%1,%2,%3}, [%4];"
                 : "=r"(r[0]), "=r"(r[1]), "=r"(r[2]), "=r"(r[3]) : "r"(addr));
}
__device__ __forceinline__ void mma16816(float* d, const uint32_t* a, uint32_t b0, uint32_t b1) {
    asm volatile(
        "mma.sync.aligned.m16n8k16.row.col.f32.f16.f16.f32 "
        "{%0,%1,%2,%3}, {%4,%5,%6,%7}, {%8,%9}, {%0,%1,%2,%3};"
        : "+f"(d[0]), "+f"(d[1]), "+f"(d[2]), "+f"(d[3])
        : "r"(a[0]), "r"(a[1]), "r"(a[2]), "r"(a[3]), "r"(b0), "r"(b1));
}
__device__ __forceinline__ float elu1(float x) { return x > 0.f ? x + 1.f : __expf(x); }
__device__ __forceinline__ float fast_tanh(float x) {
    float y;
    asm("tanh.approx.f32 %0, %1;" : "=f"(y) : "f"(x));
    return y;
}
__device__ __forceinline__ float gelu(float v) {
    float t = 0.7978845608028654f * (v + 0.044715f * v * v * v);
    return 0.5f * v * (1.0f + fast_tanh(t));
}

// ---------------- small kernels ------------------------------------------
__global__ void zero_kernel() {
    int i = blockIdx.x * blockDim.x + threadIdx.x;
    if (i < NB * H) { g_KV[i] = 0.f; g_Ksum[i] = 0.f; }
}

// x fp32 -> [hi | lo] fp16
__global__ __launch_bounds__(256) void conv_x_kernel(const float* __restrict__ x) {
    int idx = blockIdx.x * 256 + threadIdx.x;
    int m = idx >> 8;
    int k = (idx & 255) << 2;
    float4 v = *(const float4*)&x[(size_t)m * H + k];
    __half h0 = __float2half(v.x), h1 = __float2half(v.y);
    __half h2 = __float2half(v.z), h3 = __float2half(v.w);
    __half l0 = __float2half(v.x - __half2float(h0));
    __half l1 = __float2half(v.y - __half2float(h1));
    __half l2 = __float2half(v.z - __half2float(h2));
    __half l3 = __float2half(v.w - __half2float(h3));
    __half* row = &g_Ax[(size_t)m * KPA];
    __half2* p;
    p = (__half2*)&row[k];        p[0] = {h0, h1}; p[1] = {h2, h3};
    p = (__half2*)&row[1024 + k]; p[0] = {l0, l1}; p[1] = {l2, l3};
}

// weights -> fp16 hi rows, K-major. K/V interleaved 64-blocks [32 K | 32 V].
__global__ __launch_bounds__(256) void conv_w_kernel(
    const float* __restrict__ wq, const float* __restrict__ wk,
    const float* __restrict__ wv, const float* __restrict__ wo) {
    int h = blockIdx.x;
    int which = blockIdx.y;
    const float* w;
    __half* row;
    if (which == 0)      { w = wq; row = &g_Bq[(size_t)h * 1024]; }
    else if (which == 1) { w = wk; row = &g_Bkv[(size_t)((h >> 5) * 64 + (h & 31)) * 1024]; }
    else if (which == 2) { w = wv; row = &g_Bkv[(size_t)((h >> 5) * 64 + 32 + (h & 31)) * 1024]; }
    else                 { w = wo; row = &g_Bo[(size_t)h * 1024]; }
    int k = threadIdx.x * 4;
    __half hi[4];
    #pragma unroll
    for (int i = 0; i < 4; i++)
        hi[i] = __float2half(__ldg(&w[(size_t)(k + i) * H + h]));
    __half2* p = (__half2*)&row[k];
    p[0] = {hi[0], hi[1]}; p[1] = {hi[2], hi[3]};
}

// V' = Qf*KV / (Qf*Ksum + 1e-6) -> [hi|lo] fp16
__global__ __launch_bounds__(256) void vprime_kernel() {
    int m = blockIdx.x;
    int bn = m / SEQ;
    int hh = threadIdx.x * 4;
    const __half2* qp = (const __half2*)&g_Qf[(size_t)m * H + hh];
    __half2 q01 = qp[0], q23 = qp[1];
    float q[4] = {__half2float(q01.x), __half2float(q01.y),
                  __half2float(q23.x), __half2float(q23.y)};
    float4 kv = *(const float4*)&g_KV[bn * H + hh];
    float4 ks = *(const float4*)&g_Ksum[bn * H + hh];
    float a[4] = {kv.x, kv.y, kv.z, kv.w};
    float b[4] = {ks.x, ks.y, ks.z, ks.w};
    __half hi[4], lo[4];
    #pragma unroll
    for (int i = 0; i < 4; i++) {
        float vp = q[i] * a[i] * (1.0f / (q[i] * b[i] + 1e-6f));
        hi[i] = __float2half(vp);
        lo[i] = __float2half(vp - __half2float(hi[i]));
    }
    __half* row = &g_Vp[(size_t)m * KPA];
    __half2* p;
    p = (__half2*)&row[hh];        p[0] = {hi[0], hi[1]}; p[1] = {hi[2], hi[3]};
    p = (__half2*)&row[1024 + hh]; p[0] = {lo[0], lo[1]}; p[1] = {lo[2], lo[3]};
}

// ---------------- HMMA GEMM ----------------------------------------------
// CTA tile 128x128, warp tile 32x64, 3-stage single-sync pipe, fp16 MMA.
// Logical K' = [A_hi | A_lo] x [B_hi | B_hi]  (chB = ch & 15)
// MODE 0: KV-GEMM (NCHT=32) -> per-channel reduction
// MODE 1: out-GEMM (NCHT=32) -> bias+gelu -> out
// MODE 2: Q-GEMM (NCHT=16, hi only) -> elu1 -> g_Qf (fp16)
template <int MODE, int NCHT>
__global__ __launch_bounds__(256, 2) void gemm_kernel(
    const float* __restrict__ b0p,
    const float* __restrict__ b1p,
    const float* __restrict__ b2p,
    float* __restrict__ outp)
{
    extern __shared__ __align__(1024) char smv[];
    const uint32_t sb = smem_u32(smv);
    const int tid = threadIdx.x;
    const int w = tid >> 5, l = tid & 31;

    const size_t m0 = (size_t)blockIdx.y * 128;
    const int n0 = blockIdx.x * 128;

    const __half* A = (MODE == 1) ? g_Vp : g_Ax;
    const __half* B = (MODE == 0) ? g_Bkv : ((MODE == 1) ? g_Bo : g_Bq);

    const char* Asrc = (const char*)A + (m0 + (tid >> 3)) * (size_t)KBA + ((tid & 7) << 4);
    const char* Bsrc = (const char*)B + ((size_t)(n0 + (tid >> 3))) * KBB + ((tid & 7) << 4);
    const uint32_t dst0 = ((tid >> 3) << 7) + ((((tid & 7) << 4)) ^ ((((tid >> 3) & 7)) << 4));

    auto load_chunk = [&](int ch, int s) {
        int chB = ch & 15;                        // [hi|hi] dedup
        uint32_t sa = sb + s * STAGE_BYTES + dst0;
        uint32_t sbm = sa + 16384;
        const char* as = Asrc + (size_t)ch * 128;
        const char* bs = Bsrc + (size_t)chB * 128;
        #pragma unroll
        for (int j = 0; j < 4; j++) cp16(sa + (j << 12), as + j * (size_t)(32 * KBA));
        #pragma unroll
        for (int j = 0; j < 4; j++) cp16(sbm + (j << 12), bs + j * (size_t)(32 * KBB));
        cpcommit();
    };

    // warp/lane geometry: warp tile 32(M) x 64(N)
    const int wm = (w & 3) << 5;
    const int wn = (w >> 2) << 6;
    const uint32_t lx = (l & 7) << 4;
    const int arow = ((l >> 3) & 1) * 8 + (l & 7);
    const uint32_t ahb = (l >> 4) & 1;
    const int brow = ((l >> 4) & 1) * 8 + (l & 7);
    const uint32_t bhb = (l >> 3) & 1;

    float acc[64];
    #pragma unroll
    for (int i = 0; i < 64; i++) acc[i] = 0.f;

    load_chunk(0, 0);
    load_chunk(1, 1);

    #pragma unroll 1
    for (int c = 0; c < NCHT; c++) {
        if (c < NCHT - 2) cpwait<1>(); else cpwait<0>();
        __syncthreads();
        if (c + 2 < NCHT) load_chunk(c + 2, (c + 2) % 3);

        const uint32_t stA = sb + (c % 3) * STAGE_BYTES;
        const uint32_t stB = stA + 16384;
        #pragma unroll
        for (int ks = 0; ks < 4; ks++) {
            const uint32_t koffA = (((uint32_t)ks << 5) | (ahb << 4)) ^ lx;
            const uint32_t koffB = (((uint32_t)ks << 5) | (bhb << 4)) ^ lx;
            uint32_t af[2][4];
            #pragma unroll
            for (int mt = 0; mt < 2; mt++)
                ldmx4(af[mt], stA + ((uint32_t)(wm + mt * 16 + arow) << 7) + koffA);
            uint32_t bf[4][4];
            #pragma unroll
            for (int j = 0; j < 4; j++)
                ldmx4(bf[j], stB + ((uint32_t)(wn + j * 16 + brow) << 7) + koffB);
            #pragma unroll
            for (int mt = 0; mt < 2; mt++)
                #pragma unroll
                for (int nt = 0; nt < 8; nt++)
                    mma16816(&acc[(mt * 8 + nt) * 4], af[mt],
                             bf[nt >> 1][(nt & 1) * 2], bf[nt >> 1][(nt & 1) * 2 + 1]);
        }
    }
    __syncthreads();   // retire last-stage reads before smem reuse

    // ------------- epilogue -------------
    const int cl = (l & 3) << 1;

    if (MODE == 0) {
        // KV tile: warp's 64 cols = [32 K-ch | 32 matching V-ch]; pair nt <-> nt+4
        const int hbase = (n0 >> 6) * 32;
        const int hw = hbase + (wn >> 1);
        const int bn = (int)(m0 / SEQ);
        float pkv[8], pks[8];
        #pragma unroll
        for (int i = 0; i < 8; i++) { pkv[i] = 0.f; pks[i] = 0.f; }
        #pragma unroll
        for (int mt = 0; mt < 2; mt++)
            #pragma unroll
            for (int nt = 0; nt < 4; nt++)
                #pragma unroll
                for (int i = 0; i < 4; i++) {
                    int hl = nt * 8 + cl + (i & 1);
                    float kf = elu1(acc[(mt * 8 + nt) * 4 + i] + __ldg(&b1p[hw + hl]));
                    float vv = acc[(mt * 8 + nt + 4) * 4 + i] + __ldg(&b2p[hw + hl]);
                    int e = nt * 2 + (i & 1);
                    pkv[e] += kf * vv;
                    pks[e] += kf;
                }
        #pragma unroll
        for (int off = 16; off >= 4; off >>= 1)
            #pragma unroll
            for (int e = 0; e < 8; e++) {
                pkv[e] += __shfl_down_sync(0xffffffffu, pkv[e], off);
                pks[e] += __shfl_down_sync(0xffffffffu, pks[e], off);
            }
        float* redkv = (float*)smv;          // [8 warps][32]
        float* redks = redkv + 8 * 32;
        if (l < 4) {
            #pragma unroll
            for (int e = 0; e < 8; e++) {
                int hl = (e >> 1) * 8 + l * 2 + (e & 1);
                redkv[w * 32 + hl] = pkv[e];
                redks[w * 32 + hl] = pks[e];
            }
        }
        __syncthreads();
        if (tid < 128) {
            int cc = tid & 63;
            int w0 = (cc >> 5) * 4;
            float* src = (tid < 64) ? redkv : redks;
            float s = 0.f;
            #pragma unroll
            for (int j = 0; j < 4; j++) s += src[(w0 + j) * 32 + (cc & 31)];
            float* dst = (tid < 64) ? &g_KV[bn * H + hbase + cc]
                                    : &g_Ksum[bn * H + hbase + cc];
            atomicAdd(dst, s);
        }
    } else {
        // MODE 2: elu1 -> g_Qf (fp16). MODE 1: gelu -> out (fp32).
        float* ep = (float*)smv;             // [128][132]
        #pragma unroll
        for (int mt = 0; mt < 2; mt++)
            #pragma unroll
            for (int nt = 0; nt < 8; nt++) {
                int c0 = wn + nt * 8 + cl;
                float bb0 = __ldg(&b0p[n0 + c0]);
                float bb1 = __ldg(&b0p[n0 + c0 + 1]);
                int r0 = wm + mt * 16 + (l >> 2);
                float v0 = acc[(mt * 8 + nt) * 4 + 0] + bb0;
                float v1 = acc[(mt * 8 + nt) * 4 + 1] + bb1;
                float v2 = acc[(mt * 8 + nt) * 4 + 2] + bb0;
                float v3 = acc[(mt * 8 + nt) * 4 + 3] + bb1;
                if (MODE == 2) { v0 = elu1(v0); v1 = elu1(v1); v2 = elu1(v2); v3 = elu1(v3); }
                else           { v0 = gelu(v0); v1 = gelu(v1); v2 = gelu(v2); v3 = gelu(v3); }
                ep[r0 * 132 + c0] = v0;        ep[r0 * 132 + c0 + 1] = v1;
                ep[(r0 + 8) * 132 + c0] = v2;  ep[(r0 + 8) * 132 + c0 + 1] = v3;
            }
        __syncthreads();
        if (MODE == 2) {
            #pragma unroll 8
            for (int i = 0; i < 64; i++) {
                int idx = i * 256 + tid;
                int rr = idx >> 7, cc = idx & 127;
                g_Qf[(m0 + rr) * H + n0 + cc] = __float2half(ep[rr * 132 + cc]);
            }
        } else {
            #pragma unroll 8
            for (int i = 0; i < 64; i++) {
                int idx = i * 256 + tid;
                int rr = idx >> 7, cc = idx & 127;
                outp[(m0 + rr) * H + n0 + cc] = ep[rr * 132 + cc];
            }
        }
    }
}

// ---------------- launch --------------------------------------------------
extern "C" void kernel_launch(void* const* d_in, const int* in_sizes, int n_in,
                              void* d_out, int out_size) {
    const float* x  = (const float*)d_in[0];
    const float* wq = (const float*)d_in[1];
    const float* bq = (const float*)d_in[2];
    const float* wk = (const float*)d_in[3];
    const float* bk = (const float*)d_in[4];
    const float* wv = (const float*)d_in[5];
    const float* bv = (const float*)d_in[6];
    const float* wo = (const float*)d_in[7];
    const float* bo = (const float*)d_in[8];
    float* out = (float*)d_out;

    cudaFuncSetAttribute(gemm_kernel<0, 32>, cudaFuncAttributeMaxDynamicSharedMemorySize, SMEM_TOTAL);
    cudaFuncSetAttribute(gemm_kernel<1, 32>, cudaFuncAttributeMaxDynamicSharedMemorySize, SMEM_TOTAL);
    cudaFuncSetAttribute(gemm_kernel<2, 16>, cudaFuncAttributeMaxDynamicSharedMemorySize, SMEM_TOTAL);

    zero_kernel<<<(NB * H + 255) / 256, 256>>>();
    conv_x_kernel<<<M_TOTAL, 256>>>(x);
    conv_w_kernel<<<dim3(1024, 4), 256>>>(wq, wk, wv, wo);

    gemm_kernel<2, 16><<<dim3(8,  M_TOTAL / 128), 256, SMEM_TOTAL>>>(bq, nullptr, nullptr, nullptr);
    gemm_kernel<0, 32><<<dim3(16, M_TOTAL / 128), 256, SMEM_TOTAL>>>(nullptr, bk, bv, nullptr);
    vprime_kernel<<<M_TOTAL, 256>>>();
    gemm_kernel<1, 32><<<dim3(8,  M_TOTAL / 128), 256, SMEM_TOTAL>>>(bo, nullptr, nullptr, out);
}

// round 8
// speedup vs baseline: 8.5748x; 1.5894x over previous
#include <cuda_runtime.h>
#include <cuda_fp16.h>
#include <cstdint>
#include <math.h>

#define M_TOTAL 32768
#define SEQ     8192
#define H       1024
#define NB      4
#define KBA     2048                 // bytes per A row (1024 fp16)
#define KBB     2048                 // bytes per B row (1024 fp16)
#define NCH     16                   // 16 K-chunks of 64 fp16 (128B)
#define STAGE_BYTES 32768            // 16KB A + 16KB B
#define SMEM_TOTAL (3*STAGE_BYTES)   // 96KB

// ---------------- scratch -----------------------------------------------
__device__ __half g_Ax[(size_t)M_TOTAL * H];     // x, fp16
__device__ __half g_Vp[(size_t)M_TOTAL * H];     // V', fp16
__device__ __half g_Qf[(size_t)M_TOTAL * H];     // elu(q)+1, fp16
__device__ __half g_Bqkv[(size_t)3072 * H];      // [Q rows | K/V interleaved rows]
__device__ __half g_Bo [(size_t)1024 * H];       // out weights
__device__ float  g_KV[NB * H];
__device__ float  g_Ksum[NB * H];

// ---------------- helpers ------------------------------------------------
__device__ __forceinline__ uint32_t smem_u32(const void* p) {
    uint32_t a;
    asm("{ .reg .u64 t; cvta.to.shared.u64 t, %1; cvt.u32.u64 %0, t; }" : "=r"(a) : "l"(p));
    return a;
}
__device__ __forceinline__ void cp16(uint32_t dst, const void* src) {
    asm volatile("cp.async.cg.shared.global [%0], [%1], 16;" :: "r"(dst), "l"(src));
}
__device__ __forceinline__ void cpcommit() {
    asm volatile("cp.async.commit_group;" ::: "memory");
}
template <int N> __device__ __forceinline__ void cpwait() {
    asm volatile("cp.async.wait_group %0;" :: "n"(N) : "memory");
}
__device__ __forceinline__ void ldmx4(uint32_t* r, uint32_t addr) {
    asm volatile("ldmatrix.sync.aligned.m8n8.x4.shared.b16 {%0,%1,%2,%3}, [%4];"
                 : "=r"(r[0]), "=r"(r[1]), "=r"(r[2]), "=r"(r[3]) : "r"(addr));
}
__device__ __forceinline__ void mma16816(float* d, const uint32_t* a, uint32_t b0, uint32_t b1) {
    asm volatile(
        "mma.sync.aligned.m16n8k16.row.col.f32.f16.f16.f32 "
        "{%0,%1,%2,%3}, {%4,%5,%6,%7}, {%8,%9}, {%0,%1,%2,%3};"
        : "+f"(d[0]), "+f"(d[1]), "+f"(d[2]), "+f"(d[3])
        : "r"(a[0]), "r"(a[1]), "r"(a[2]), "r"(a[3]), "r"(b0), "r"(b1));
}
__device__ __forceinline__ float elu1(float x) { return x > 0.f ? x + 1.f : __expf(x); }
__device__ __forceinline__ float fast_tanh(float x) {
    float y;
    asm("tanh.approx.f32 %0, %1;" : "=f"(y) : "f"(x));
    return y;
}
__device__ __forceinline__ float gelu(float v) {
    float t = 0.7978845608028654f * (v + 0.044715f * v * v * v);
    return 0.5f * v * (1.0f + fast_tanh(t));
}

// ---------------- small kernels ------------------------------------------
__global__ void zero_kernel() {
    int i = blockIdx.x * blockDim.x + threadIdx.x;
    if (i < NB * H) { g_KV[i] = 0.f; g_Ksum[i] = 0.f; }
}

// x fp32 -> fp16
__global__ __launch_bounds__(256) void conv_x_kernel(const float* __restrict__ x) {
    size_t idx = (size_t)blockIdx.x * 256 + threadIdx.x;
    size_t k = idx << 2;
    float4 v = *(const float4*)&x[k];
    __half2* p = (__half2*)&g_Ax[k];
    p[0] = {__float2half(v.x), __float2half(v.y)};
    p[1] = {__float2half(v.z), __float2half(v.w)};
}

// weights -> fp16 rows, K-major. B layout: rows 0-1023 = Q;
// rows 1024-3071 = K/V interleaved 64-blocks [32 K-ch | 32 matching V-ch].
__global__ __launch_bounds__(256) void conv_w_kernel(
    const float* __restrict__ wq, const float* __restrict__ wk,
    const float* __restrict__ wv, const float* __restrict__ wo) {
    int h = blockIdx.x;
    int which = blockIdx.y;
    const float* w;
    __half* row;
    if (which == 0)      { w = wq; row = &g_Bqkv[(size_t)h * H]; }
    else if (which == 1) { w = wk; row = &g_Bqkv[(size_t)(1024 + (h >> 5) * 64 + (h & 31)) * H]; }
    else if (which == 2) { w = wv; row = &g_Bqkv[(size_t)(1024 + (h >> 5) * 64 + 32 + (h & 31)) * H]; }
    else                 { w = wo; row = &g_Bo[(size_t)h * H]; }
    int k = threadIdx.x * 4;
    __half hi[4];
    #pragma unroll
    for (int i = 0; i < 4; i++)
        hi[i] = __float2half(__ldg(&w[(size_t)(k + i) * H + h]));
    __half2* p = (__half2*)&row[k];
    p[0] = {hi[0], hi[1]}; p[1] = {hi[2], hi[3]};
}

// V' = Qf*KV / (Qf*Ksum + 1e-6) -> fp16
__global__ __launch_bounds__(256) void vprime_kernel() {
    int m = blockIdx.x;
    int bn = m / SEQ;
    int hh = threadIdx.x * 4;
    const __half2* qp = (const __half2*)&g_Qf[(size_t)m * H + hh];
    __half2 q01 = qp[0], q23 = qp[1];
    float q[4] = {__half2float(q01.x), __half2float(q01.y),
                  __half2float(q23.x), __half2float(q23.y)};
    float4 kv = *(const float4*)&g_KV[bn * H + hh];
    float4 ks = *(const float4*)&g_Ksum[bn * H + hh];
    float a[4] = {kv.x, kv.y, kv.z, kv.w};
    float b[4] = {ks.x, ks.y, ks.z, ks.w};
    __half hi[4];
    #pragma unroll
    for (int i = 0; i < 4; i++)
        hi[i] = __float2half(q[i] * a[i] * (1.0f / (q[i] * b[i] + 1e-6f)));
    __half2* p = (__half2*)&g_Vp[(size_t)m * H + hh];
    p[0] = {hi[0], hi[1]}; p[1] = {hi[2], hi[3]};
}

// ---------------- HMMA GEMM ----------------------------------------------
// CTA tile 128x128, warp tile 32x64, 3-stage single-sync pipe, fp16, K=1024.
// MODE 0: fused QKV-GEMM (N=3072). n0<1024: Q tile -> elu1 -> g_Qf.
//         n0>=1024: KV tile -> per-channel reduction.
// MODE 1: out-GEMM (N=1024) -> bias+gelu -> out.
template <int MODE>
__global__ __launch_bounds__(256, 2) void gemm_kernel(
    const float* __restrict__ b0p,
    const float* __restrict__ b1p,
    const float* __restrict__ b2p,
    float* __restrict__ outp)
{
    extern __shared__ __align__(1024) char smv[];
    const uint32_t sb = smem_u32(smv);
    const int tid = threadIdx.x;
    const int w = tid >> 5, l = tid & 31;

    const size_t m0 = (size_t)blockIdx.y * 128;
    const int n0 = blockIdx.x * 128;

    const __half* A = (MODE == 1) ? g_Vp : g_Ax;
    const __half* B = (MODE == 1) ? g_Bo : g_Bqkv;

    const char* Asrc = (const char*)A + (m0 + (tid >> 3)) * (size_t)KBA + ((tid & 7) << 4);
    const char* Bsrc = (const char*)B + ((size_t)(n0 + (tid >> 3))) * KBB + ((tid & 7) << 4);
    const uint32_t dst0 = ((tid >> 3) << 7) + ((((tid & 7) << 4)) ^ ((((tid >> 3) & 7)) << 4));

    auto load_chunk = [&](int ch, int s) {
        uint32_t sa = sb + s * STAGE_BYTES + dst0;
        uint32_t sbm = sa + 16384;
        const char* as = Asrc + (size_t)ch * 128;
        const char* bs = Bsrc + (size_t)ch * 128;
        #pragma unroll
        for (int j = 0; j < 4; j++) cp16(sa + (j << 12), as + j * (size_t)(32 * KBA));
        #pragma unroll
        for (int j = 0; j < 4; j++) cp16(sbm + (j << 12), bs + j * (size_t)(32 * KBB));
        cpcommit();
    };

    // warp/lane geometry: warp tile 32(M) x 64(N)
    const int wm = (w & 3) << 5;
    const int wn = (w >> 2) << 6;
    const uint32_t lx = (l & 7) << 4;
    const int arow = ((l >> 3) & 1) * 8 + (l & 7);
    const uint32_t ahb = (l >> 4) & 1;
    const int brow = ((l >> 4) & 1) * 8 + (l & 7);
    const uint32_t bhb = (l >> 3) & 1;

    float acc[64];
    #pragma unroll
    for (int i = 0; i < 64; i++) acc[i] = 0.f;

    load_chunk(0, 0);
    load_chunk(1, 1);

    #pragma unroll 1
    for (int c = 0; c < NCH; c++) {
        if (c < NCH - 2) cpwait<1>(); else cpwait<0>();
        __syncthreads();
        if (c + 2 < NCH) load_chunk(c + 2, (c + 2) % 3);

        const uint32_t stA = sb + (c % 3) * STAGE_BYTES;
        const uint32_t stB = stA + 16384;
        #pragma unroll
        for (int ks = 0; ks < 4; ks++) {
            const uint32_t koffA = (((uint32_t)ks << 5) | (ahb << 4)) ^ lx;
            const uint32_t koffB = (((uint32_t)ks << 5) | (bhb << 4)) ^ lx;
            uint32_t af[2][4];
            #pragma unroll
            for (int mt = 0; mt < 2; mt++)
                ldmx4(af[mt], stA + ((uint32_t)(wm + mt * 16 + arow) << 7) + koffA);
            uint32_t bf[4][4];
            #pragma unroll
            for (int j = 0; j < 4; j++)
                ldmx4(bf[j], stB + ((uint32_t)(wn + j * 16 + brow) << 7) + koffB);
            #pragma unroll
            for (int mt = 0; mt < 2; mt++)
                #pragma unroll
                for (int nt = 0; nt < 8; nt++)
                    mma16816(&acc[(mt * 8 + nt) * 4], af[mt],
                             bf[nt >> 1][(nt & 1) * 2], bf[nt >> 1][(nt & 1) * 2 + 1]);
        }
    }
    __syncthreads();   // retire last-stage reads before smem reuse

    // ------------- epilogue -------------
    const int cl = (l & 3) << 1;

    if (MODE == 0 && n0 >= 1024) {
        // KV tile: warp's 64 cols = [32 K-ch | 32 matching V-ch]; pair nt <-> nt+4
        const int hbase = ((n0 - 1024) >> 6) * 32;
        const int hw = hbase + (wn >> 1);
        const int bn = (int)(m0 / SEQ);
        float pkv[8], pks[8];
        #pragma unroll
        for (int i = 0; i < 8; i++) { pkv[i] = 0.f; pks[i] = 0.f; }
        #pragma unroll
        for (int mt = 0; mt < 2; mt++)
            #pragma unroll
            for (int nt = 0; nt < 4; nt++)
                #pragma unroll
                for (int i = 0; i < 4; i++) {
                    int hl = nt * 8 + cl + (i & 1);
                    float kf = elu1(acc[(mt * 8 + nt) * 4 + i] + __ldg(&b1p[hw + hl]));
                    float vv = acc[(mt * 8 + nt + 4) * 4 + i] + __ldg(&b2p[hw + hl]);
                    int e = nt * 2 + (i & 1);
                    pkv[e] += kf * vv;
                    pks[e] += kf;
                }
        #pragma unroll
        for (int off = 16; off >= 4; off >>= 1)
            #pragma unroll
            for (int e = 0; e < 8; e++) {
                pkv[e] += __shfl_down_sync(0xffffffffu, pkv[e], off);
                pks[e] += __shfl_down_sync(0xffffffffu, pks[e], off);
            }
        float* redkv = (float*)smv;          // [8 warps][32]
        float* redks = redkv + 8 * 32;
        if (l < 4) {
            #pragma unroll
            for (int e = 0; e < 8; e++) {
                int hl = (e >> 1) * 8 + l * 2 + (e & 1);
                redkv[w * 32 + hl] = pkv[e];
                redks[w * 32 + hl] = pks[e];
            }
        }
        __syncthreads();
        if (tid < 128) {
            int cc = tid & 63;
            int w0 = (cc >> 5) * 4;
            float* src = (tid < 64) ? redkv : redks;
            float s = 0.f;
            #pragma unroll
            for (int j = 0; j < 4; j++) s += src[(w0 + j) * 32 + (cc & 31)];
            float* dst = (tid < 64) ? &g_KV[bn * H + hbase + cc]
                                    : &g_Ksum[bn * H + hbase + cc];
            atomicAdd(dst, s);
        }
    } else {
        // Q tile (MODE 0, elu1 -> g_Qf fp16) or out tile (MODE 1, gelu -> fp32)
        float* ep = (float*)smv;             // [128][132]
        #pragma unroll
        for (int mt = 0; mt < 2; mt++)
            #pragma unroll
            for (int nt = 0; nt < 8; nt++) {
                int c0 = wn + nt * 8 + cl;
                float bb0 = __ldg(&b0p[n0 + c0]);
                float bb1 = __ldg(&b0p[n0 + c0 + 1]);
                int r0 = wm + mt * 16 + (l >> 2);
                float v0 = acc[(mt * 8 + nt) * 4 + 0] + bb0;
                float v1 = acc[(mt * 8 + nt) * 4 + 1] + bb1;
                float v2 = acc[(mt * 8 + nt) * 4 + 2] + bb0;
                float v3 = acc[(mt * 8 + nt) * 4 + 3] + bb1;
                if (MODE == 0) { v0 = elu1(v0); v1 = elu1(v1); v2 = elu1(v2); v3 = elu1(v3); }
                else           { v0 = gelu(v0); v1 = gelu(v1); v2 = gelu(v2); v3 = gelu(v3); }
                ep[r0 * 132 + c0] = v0;        ep[r0 * 132 + c0 + 1] = v1;
                ep[(r0 + 8) * 132 + c0] = v2;  ep[(r0 + 8) * 132 + c0 + 1] = v3;
            }
        __syncthreads();
        if (MODE == 0) {
            #pragma unroll 8
            for (int i = 0; i < 64; i++) {
                int idx = i * 256 + tid;
                int rr = idx >> 7, cc = idx & 127;
                g_Qf[(m0 + rr) * H + n0 + cc] = __float2half(ep[rr * 132 + cc]);
            }
        } else {
            #pragma unroll 8
            for (int i = 0; i < 64; i++) {
                int idx = i * 256 + tid;
                int rr = idx >> 7, cc = idx & 127;
                outp[(m0 + rr) * H + n0 + cc] = ep[rr * 132 + cc];
            }
        }
    }
}

// ---------------- launch --------------------------------------------------
extern "C" void kernel_launch(void* const* d_in, const int* in_sizes, int n_in,
                              void* d_out, int out_size) {
    const float* x  = (const float*)d_in[0];
    const float* wq = (const float*)d_in[1];
    const float* bq = (const float*)d_in[2];
    const float* wk = (const float*)d_in[3];
    const float* bk = (const float*)d_in[4];
    const float* wv = (const float*)d_in[5];
    const float* bv = (const float*)d_in[6];
    const float* wo = (const float*)d_in[7];
    const float* bo = (const float*)d_in[8];
    float* out = (float*)d_out;

    cudaFuncSetAttribute(gemm_kernel<0>, cudaFuncAttributeMaxDynamicSharedMemorySize, SMEM_TOTAL);
    cudaFuncSetAttribute(gemm_kernel<1>, cudaFuncAttributeMaxDynamicSharedMemorySize, SMEM_TOTAL);

    zero_kernel<<<(NB * H + 255) / 256, 256>>>();
    conv_x_kernel<<<M_TOTAL * H / 1024, 256>>>(x);
    conv_w_kernel<<<dim3(1024, 4), 256>>>(wq, wk, wv, wo);

    gemm_kernel<0><<<dim3(24, M_TOTAL / 128), 256, SMEM_TOTAL>>>(bq, bk, bv, nullptr);
    vprime_kernel<<<M_TOTAL, 256>>>();
    gemm_kernel<1><<<dim3(8, M_TOTAL / 128), 256, SMEM_TOTAL>>>(bo, nullptr, nullptr, out);
}

// round 9
// speedup vs baseline: 8.9391x; 1.0425x over previous
#include <cuda_runtime.h>
#include <cuda_fp16.h>
#include <cstdint>
#include <math.h>

#define M_TOTAL 32768
#define SEQ     8192
#define H       1024
#define NB      4
#define KBA     2048                 // bytes per A row (1024 fp16)
#define KBB     2048                 // bytes per B row (1024 fp16)
#define NCH     16                   // 16 K-chunks of 64 fp16 (128B)
#define STAGE_BYTES 32768            // 16KB A + 16KB B
#define SMEM_TOTAL (3*STAGE_BYTES)   // 96KB

// ---------------- scratch -----------------------------------------------
__device__ __half g_Ax[(size_t)M_TOTAL * H];     // x, fp16
__device__ __half g_Vp[(size_t)M_TOTAL * H];     // V', fp16
__device__ __half g_Qf[(size_t)M_TOTAL * H];     // elu(q)+1, fp16
__device__ __half g_Bqkv[(size_t)3072 * H];      // [Q rows | K/V interleaved rows]
__device__ __half g_Bo [(size_t)1024 * H];       // out weights
__device__ float  g_KV[NB * H];
__device__ float  g_Ksum[NB * H];

// ---------------- helpers ------------------------------------------------
__device__ __forceinline__ uint32_t smem_u32(const void* p) {
    uint32_t a;
    asm("{ .reg .u64 t; cvta.to.shared.u64 t, %1; cvt.u32.u64 %0, t; }" : "=r"(a) : "l"(p));
    return a;
}
__device__ __forceinline__ void cp16(uint32_t dst, const void* src) {
    asm volatile("cp.async.cg.shared.global [%0], [%1], 16;" :: "r"(dst), "l"(src));
}
__device__ __forceinline__ void cpcommit() {
    asm volatile("cp.async.commit_group;" ::: "memory");
}
template <int N> __device__ __forceinline__ void cpwait() {
    asm volatile("cp.async.wait_group %0;" :: "n"(N) : "memory");
}
__device__ __forceinline__ void ldmx4(uint32_t* r, uint32_t addr) {
    asm volatile("ldmatrix.sync.aligned.m8n8.x4.shared.b16 {%0,%1,%2,%3}, [%4];"
                 : "=r"(r[0]), "=r"(r[1]), "=r"(r[2]), "=r"(r[3]) : "r"(addr));
}
__device__ __forceinline__ void mma16816(float* d, const uint32_t* a, uint32_t b0, uint32_t b1) {
    asm volatile(
        "mma.sync.aligned.m16n8k16.row.col.f32.f16.f16.f32 "
        "{%0,%1,%2,%3}, {%4,%5,%6,%7}, {%8,%9}, {%0,%1,%2,%3};"
        : "+f"(d[0]), "+f"(d[1]), "+f"(d[2]), "+f"(d[3])
        : "r"(a[0]), "r"(a[1]), "r"(a[2]), "r"(a[3]), "r"(b0), "r"(b1));
}
__device__ __forceinline__ float elu1(float x) { return x > 0.f ? x + 1.f : __expf(x); }
__device__ __forceinline__ float fast_tanh(float x) {
    float y;
    asm("tanh.approx.f32 %0, %1;" : "=f"(y) : "f"(x));
    return y;
}
__device__ __forceinline__ float gelu(float v) {
    float t = 0.7978845608028654f * (v + 0.044715f * v * v * v);
    return 0.5f * v * (1.0f + fast_tanh(t));
}

// ---------------- small kernels ------------------------------------------
__global__ void zero_kernel() {
    int i = blockIdx.x * blockDim.x + threadIdx.x;
    if (i < NB * H) { g_KV[i] = 0.f; g_Ksum[i] = 0.f; }
}

// x fp32 -> fp16
__global__ __launch_bounds__(256) void conv_x_kernel(const float* __restrict__ x) {
    size_t idx = (size_t)blockIdx.x * 256 + threadIdx.x;
    size_t k = idx << 2;
    float4 v = *(const float4*)&x[k];
    __half2* p = (__half2*)&g_Ax[k];
    p[0] = {__float2half(v.x), __float2half(v.y)};
    p[1] = {__float2half(v.z), __float2half(v.w)};
}

// weights -> fp16 rows via tiled 64x64 smem transpose (coalesced both ways).
// B layout: rows 0-1023 = Q; rows 1024-3071 = K/V interleaved 64-blocks
// [32 K-ch | 32 matching V-ch]. Separate g_Bo for output weights.
__global__ __launch_bounds__(256) void conv_w_kernel(
    const float* __restrict__ wq, const float* __restrict__ wk,
    const float* __restrict__ wv, const float* __restrict__ wo) {
    __shared__ float s[64][65];
    const int tid = threadIdx.x;
    const int which = blockIdx.y;
    const int k0 = (blockIdx.x >> 4) * 64;
    const int h0 = (blockIdx.x & 15) * 64;
    const float* w = (which == 0) ? wq : (which == 1) ? wk : (which == 2) ? wv : wo;

    // coalesced read: 64 rows (k) x 64 cols (h)
    #pragma unroll
    for (int pass = 0; pass < 4; pass++) {
        int r = (tid >> 4) + pass * 16;
        int c4 = (tid & 15) << 2;
        float4 v = *(const float4*)&w[(size_t)(k0 + r) * H + h0 + c4];
        s[r][c4 + 0] = v.x; s[r][c4 + 1] = v.y;
        s[r][c4 + 2] = v.z; s[r][c4 + 3] = v.w;
    }
    __syncthreads();

    // coalesced write: per-h rows of fp16, 16B segments
    #pragma unroll
    for (int pass = 0; pass < 2; pass++) {
        int idx = pass * 256 + tid;            // 0..511
        int hh = idx >> 3;                     // 0..63
        int seg = idx & 7;                     // 0..7 (8 k-values each)
        int h = h0 + hh;
        __half* row;
        if (which == 0)      row = &g_Bqkv[(size_t)h * H];
        else if (which == 1) row = &g_Bqkv[(size_t)(1024 + (h >> 5) * 64 + (h & 31)) * H];
        else if (which == 2) row = &g_Bqkv[(size_t)(1024 + (h >> 5) * 64 + 32 + (h & 31)) * H];
        else                 row = &g_Bo[(size_t)h * H];
        int kk = seg * 8;
        __half2 h4[4];
        #pragma unroll
        for (int i = 0; i < 4; i++)
            h4[i] = {__float2half(s[kk + 2 * i][hh]), __float2half(s[kk + 2 * i + 1][hh])};
        *(uint4*)&row[k0 + kk] = *(uint4*)h4;
    }
}

// V' = Qf*KV / (Qf*Ksum + 1e-6) -> fp16
__global__ __launch_bounds__(256) void vprime_kernel() {
    int m = blockIdx.x;
    int bn = m / SEQ;
    int hh = threadIdx.x * 4;
    const __half2* qp = (const __half2*)&g_Qf[(size_t)m * H + hh];
    __half2 q01 = qp[0], q23 = qp[1];
    float q[4] = {__half2float(q01.x), __half2float(q01.y),
                  __half2float(q23.x), __half2float(q23.y)};
    float4 kv = *(const float4*)&g_KV[bn * H + hh];
    float4 ks = *(const float4*)&g_Ksum[bn * H + hh];
    float a[4] = {kv.x, kv.y, kv.z, kv.w};
    float b[4] = {ks.x, ks.y, ks.z, ks.w};
    __half hi[4];
    #pragma unroll
    for (int i = 0; i < 4; i++)
        hi[i] = __float2half(q[i] * a[i] * (1.0f / (q[i] * b[i] + 1e-6f)));
    __half2* p = (__half2*)&g_Vp[(size_t)m * H + hh];
    p[0] = {hi[0], hi[1]}; p[1] = {hi[2], hi[3]};
}

// ---------------- HMMA GEMM ----------------------------------------------
// CTA tile 128x128, 128 threads (4 warps), warp tile 64x64, 3-stage pipe.
// MODE 0: fused QKV-GEMM (N=3072). n0<1024: Q tile -> elu1 -> g_Qf.
//         n0>=1024: KV tile -> per-channel reduction.
// MODE 1: out-GEMM (N=1024) -> bias+gelu -> out.
template <int MODE>
__global__ __launch_bounds__(128, 2) void gemm_kernel(
    const float* __restrict__ b0p,
    const float* __restrict__ b1p,
    const float* __restrict__ b2p,
    float* __restrict__ outp)
{
    extern __shared__ __align__(1024) char smv[];
    const uint32_t sb = smem_u32(smv);
    const int tid = threadIdx.x;
    const int w = tid >> 5, l = tid & 31;

    const size_t m0 = (size_t)blockIdx.y * 128;
    const int n0 = blockIdx.x * 128;

    const __half* A = (MODE == 1) ? g_Vp : g_Ax;
    const __half* B = (MODE == 1) ? g_Bo : g_Bqkv;

    // cp.async: 128 threads cover 128 rows x 128B for A and B each
    const char* Asrc = (const char*)A + (m0 + (tid >> 3)) * (size_t)KBA + ((tid & 7) << 4);
    const char* Bsrc = (const char*)B + ((size_t)(n0 + (tid >> 3))) * KBB + ((tid & 7) << 4);
    const uint32_t dst0 = ((tid >> 3) << 7) + ((((tid & 7) << 4)) ^ ((((tid >> 3) & 7)) << 4));

    auto load_chunk = [&](int ch, int s) {
        uint32_t sa = sb + s * STAGE_BYTES + dst0;
        uint32_t sbm = sa + 16384;
        const char* as = Asrc + (size_t)ch * 128;
        const char* bs = Bsrc + (size_t)ch * 128;
        #pragma unroll
        for (int j = 0; j < 8; j++) cp16(sa + (j << 11), as + j * (size_t)(16 * KBA));
        #pragma unroll
        for (int j = 0; j < 8; j++) cp16(sbm + (j << 11), bs + j * (size_t)(16 * KBB));
        cpcommit();
    };

    // warp/lane geometry: warp tile 64(M) x 64(N), warp grid 2x2
    const int wm = (w & 1) << 6;
    const int wn = (w >> 1) << 6;
    const uint32_t lx = (l & 7) << 4;
    const int arow = ((l >> 3) & 1) * 8 + (l & 7);
    const uint32_t ahb = (l >> 4) & 1;
    const int brow = ((l >> 4) & 1) * 8 + (l & 7);
    const uint32_t bhb = (l >> 3) & 1;

    float acc[128];
    #pragma unroll
    for (int i = 0; i < 128; i++) acc[i] = 0.f;

    load_chunk(0, 0);
    load_chunk(1, 1);

    #pragma unroll 1
    for (int c = 0; c < NCH; c++) {
        if (c < NCH - 2) cpwait<1>(); else cpwait<0>();
        __syncthreads();
        if (c + 2 < NCH) load_chunk(c + 2, (c + 2) % 3);

        const uint32_t stA = sb + (c % 3) * STAGE_BYTES;
        const uint32_t stB = stA + 16384;
        #pragma unroll
        for (int ks = 0; ks < 4; ks++) {
            const uint32_t koffA = (((uint32_t)ks << 5) | (ahb << 4)) ^ lx;
            const uint32_t koffB = (((uint32_t)ks << 5) | (bhb << 4)) ^ lx;
            uint32_t af[4][4];
            #pragma unroll
            for (int mt = 0; mt < 4; mt++)
                ldmx4(af[mt], stA + ((uint32_t)(wm + mt * 16 + arow) << 7) + koffA);
            uint32_t bf[4][4];
            #pragma unroll
            for (int j = 0; j < 4; j++)
                ldmx4(bf[j], stB + ((uint32_t)(wn + j * 16 + brow) << 7) + koffB);
            #pragma unroll
            for (int mt = 0; mt < 4; mt++)
                #pragma unroll
                for (int nt = 0; nt < 8; nt++)
                    mma16816(&acc[(mt * 8 + nt) * 4], af[mt],
                             bf[nt >> 1][(nt & 1) * 2], bf[nt >> 1][(nt & 1) * 2 + 1]);
        }
    }
    __syncthreads();   // retire last-stage reads before smem reuse

    // ------------- epilogue -------------
    const int cl = (l & 3) << 1;

    if (MODE == 0 && n0 >= 1024) {
        // KV tile: warp's 64 cols = [32 K-ch | 32 matching V-ch]; pair nt <-> nt+4
        const int hbase = ((n0 - 1024) >> 6) * 32;
        const int hw = hbase + (wn >> 1);
        const int bn = (int)(m0 / SEQ);
        float pkv[8], pks[8];
        #pragma unroll
        for (int i = 0; i < 8; i++) { pkv[i] = 0.f; pks[i] = 0.f; }
        #pragma unroll
        for (int mt = 0; mt < 4; mt++)
            #pragma unroll
            for (int nt = 0; nt < 4; nt++)
                #pragma unroll
                for (int i = 0; i < 4; i++) {
                    int hl = nt * 8 + cl + (i & 1);
                    float kf = elu1(acc[(mt * 8 + nt) * 4 + i] + __ldg(&b1p[hw + hl]));
                    float vv = acc[(mt * 8 + nt + 4) * 4 + i] + __ldg(&b2p[hw + hl]);
                    int e = nt * 2 + (i & 1);
                    pkv[e] += kf * vv;
                    pks[e] += kf;
                }
        #pragma unroll
        for (int off = 16; off >= 4; off >>= 1)
            #pragma unroll
            for (int e = 0; e < 8; e++) {
                pkv[e] += __shfl_down_sync(0xffffffffu, pkv[e], off);
                pks[e] += __shfl_down_sync(0xffffffffu, pks[e], off);
            }
        float* redkv = (float*)smv;          // [4 warps][32]
        float* redks = redkv + 4 * 32;
        if (l < 4) {
            #pragma unroll
            for (int e = 0; e < 8; e++) {
                int hl = (e >> 1) * 8 + l * 2 + (e & 1);
                redkv[w * 32 + hl] = pkv[e];
                redks[w * 32 + hl] = pks[e];
            }
        }
        __syncthreads();
        {
            int cc = tid & 63;
            int w0 = (cc >> 5) * 2;          // warps {0,1} cols 0-63; {2,3} cols 64-127
            float* src = (tid < 64) ? redkv : redks;
            float s = src[w0 * 32 + (cc & 31)] + src[(w0 + 1) * 32 + (cc & 31)];
            float* dst = (tid < 64) ? &g_KV[bn * H + hbase + cc]
                                    : &g_Ksum[bn * H + hbase + cc];
            atomicAdd(dst, s);
        }
    } else {
        // Q tile (MODE 0, elu1 -> g_Qf fp16) or out tile (MODE 1, gelu -> fp32)
        float* ep = (float*)smv;             // [128][132]
        #pragma unroll
        for (int mt = 0; mt < 4; mt++)
            #pragma unroll
            for (int nt = 0; nt < 8; nt++) {
                int c0 = wn + nt * 8 + cl;
                float bb0 = __ldg(&b0p[n0 + c0]);
                float bb1 = __ldg(&b0p[n0 + c0 + 1]);
                int r0 = wm + mt * 16 + (l >> 2);
                float v0 = acc[(mt * 8 + nt) * 4 + 0] + bb0;
                float v1 = acc[(mt * 8 + nt) * 4 + 1] + bb1;
                float v2 = acc[(mt * 8 + nt) * 4 + 2] + bb0;
                float v3 = acc[(mt * 8 + nt) * 4 + 3] + bb1;
                if (MODE == 0) { v0 = elu1(v0); v1 = elu1(v1); v2 = elu1(v2); v3 = elu1(v3); }
                else           { v0 = gelu(v0); v1 = gelu(v1); v2 = gelu(v2); v3 = gelu(v3); }
                ep[r0 * 132 + c0] = v0;        ep[r0 * 132 + c0 + 1] = v1;
                ep[(r0 + 8) * 132 + c0] = v2;  ep[(r0 + 8) * 132 + c0 + 1] = v3;
            }
        __syncthreads();
        if (MODE == 0) {
            #pragma unroll 8
            for (int i = 0; i < 128; i++) {
                int idx = i * 128 + tid;
                int rr = idx >> 7, cc = idx & 127;
                g_Qf[(m0 + rr) * H + n0 + cc] = __float2half(ep[rr * 132 + cc]);
            }
        } else {
            #pragma unroll 8
            for (int i = 0; i < 128; i++) {
                int idx = i * 128 + tid;
                int rr = idx >> 7, cc = idx & 127;
                outp[(m0 + rr) * H + n0 + cc] = ep[rr * 132 + cc];
            }
        }
    }
}

// ---------------- launch --------------------------------------------------
extern "C" void kernel_launch(void* const* d_in, const int* in_sizes, int n_in,
                              void* d_out, int out_size) {
    const float* x  = (const float*)d_in[0];
    const float* wq = (const float*)d_in[1];
    const float* bq = (const float*)d_in[2];
    const float* wk = (const float*)d_in[3];
    const float* bk = (const float*)d_in[4];
    const float* wv = (const float*)d_in[5];
    const float* bv = (const float*)d_in[6];
    const float* wo = (const float*)d_in[7];
    const float* bo = (const float*)d_in[8];
    float* out = (float*)d_out;

    cudaFuncSetAttribute(gemm_kernel<0>, cudaFuncAttributeMaxDynamicSharedMemorySize, SMEM_TOTAL);
    cudaFuncSetAttribute(gemm_kernel<1>, cudaFuncAttributeMaxDynamicSharedMemorySize, SMEM_TOTAL);

    zero_kernel<<<(NB * H + 255) / 256, 256>>>();
    conv_x_kernel<<<M_TOTAL * H / 1024, 256>>>(x);
    conv_w_kernel<<<dim3(256, 4), 256>>>(wq, wk, wv, wo);

    gemm_kernel<0><<<dim3(24, M_TOTAL / 128), 128, SMEM_TOTAL>>>(bq, bk, bv, nullptr);
    vprime_kernel<<<M_TOTAL, 256>>>();
    gemm_kernel<1><<<dim3(8, M_TOTAL / 128), 128, SMEM_TOTAL>>>(bo, nullptr, nullptr, out);
}